// round 14
// baseline (speedup 1.0000x reference)
#include <cuda_runtime.h>
#include <cstddef>

#define NB 16
#define NPT 4096
#define NS 1024
#define NK 32
#define MROWS (NB*NS*NK)
#define FTH 512

__device__ __align__(16) float g_pprime[(size_t)NB*NPT*64];
__device__ int                 g_gidx[MROWS];
__device__ __align__(16) float g_zB[(size_t)MROWS*64];   // z1
__device__ __align__(16) float g_gmax[(size_t)NB*NS*2*128];   // per HALF-group extrema
__device__ __align__(16) float g_gmin[(size_t)NB*NS*2*128];
__device__ double              g_stat[512];
__device__ float               g_scale[320];
__device__ float               g_shift[320];
__device__ int                 g_fpsprog[NB];
__device__ int                 g_bqdone[NB*32];
__device__ int                 g_ppcnt[NB];

__device__ __forceinline__ unsigned long long pk(float lo, float hi) {
    unsigned long long r;
    asm("mov.b64 %0, {%1,%2};" : "=l"(r) : "f"(lo), "f"(hi));
    return r;
}
__device__ __forceinline__ unsigned long long ffma2(unsigned long long a, unsigned long long b, unsigned long long c) {
    unsigned long long d;
    asm("fma.rn.f32x2 %0, %1, %2, %3;" : "=l"(d) : "l"(a), "l"(b), "l"(c));
    return d;
}
__device__ __forceinline__ unsigned long long add2(unsigned long long a, unsigned long long b) {
    unsigned long long d;
    asm("add.rn.f32x2 %0, %1, %2;" : "=l"(d) : "l"(a), "l"(b));
    return d;
}
__device__ __forceinline__ unsigned long long mul2(unsigned long long a, unsigned long long b) {
    unsigned long long d;
    asm("mul.rn.f32x2 %0, %1, %2;" : "=l"(d) : "l"(a), "l"(b));
    return d;
}
__device__ __forceinline__ void upk(unsigned long long v, float& lo, float& hi) {
    asm("mov.b64 {%0,%1}, %2;" : "=f"(lo), "=f"(hi) : "l"(v));
}
__device__ __forceinline__ unsigned redux_umax(unsigned v) {
    unsigned r;
    asm("redux.sync.max.u32 %0, %1, 0xffffffff;" : "=r"(r) : "r"(v));
    return r;
}
__device__ __forceinline__ unsigned pack_bf16x2(float even, float odd) {
    unsigned d;
    asm("cvt.rn.bf16x2.f32 %0, %1, %2;" : "=r"(d) : "f"(odd), "f"(even));
    return d;
}
__device__ __forceinline__ float bf16lo_f32(unsigned p) { return __uint_as_float(p << 16); }
__device__ __forceinline__ float bf16hi_f32(unsigned p) { return __uint_as_float(p & 0xffff0000u); }

__device__ __forceinline__ void mma_bf16(float* c, const unsigned* a, const unsigned* b) {
    asm volatile("mma.sync.aligned.m16n8k16.row.col.f32.bf16.bf16.f32 "
        "{%0,%1,%2,%3}, {%4,%5,%6,%7}, {%8,%9}, {%0,%1,%2,%3};"
        : "+f"(c[0]), "+f"(c[1]), "+f"(c[2]), "+f"(c[3])
        : "r"(a[0]), "r"(a[1]), "r"(a[2]), "r"(a[3]), "r"(b[0]), "r"(b[1]));
}
__device__ __forceinline__ void spin_until(volatile int* p, int target) {
    while (*p < target) __nanosleep(64);
}

__global__ void zero_kernel() {
    int t = threadIdx.x;
    if (t < 512) { g_stat[t] = 0.0; g_bqdone[t] = 0; }
    if (t < NB) { g_fpsprog[t] = 0; g_ppcnt[t] = 0; }
}

// =================== mega front kernel with fps progress pipelining (unchanged) ===================
__global__ void __launch_bounds__(FTH) front_kernel(const float* __restrict__ xyz,
                                                    const float* __restrict__ points,
                                                    const float* __restrict__ w0,
                                                    float* __restrict__ out_newxyz) {
    extern __shared__ float dsm[];
    int bid = blockIdx.x;
    int t = threadIdx.x;

    if (bid < 16) {
        int b = bid;
        float* sx = dsm; float* sy = dsm + NPT; float* sz = dsm + 2*NPT;
        unsigned* swhi = (unsigned*)(dsm + 3*NPT);
        unsigned* swlo = swhi + 32;
        int w = t >> 5, lane = t & 31;
        const float* p = xyz + (size_t)b*NPT*3;
        for (int i = t; i < NPT; i += FTH) { sx[i]=p[3*i]; sy[i]=p[3*i+1]; sz[i]=p[3*i+2]; }
        __syncthreads();
        unsigned long long pxp[4], pyp[4], pzp[4];
        float dist[8];
        const float INF = __int_as_float(0x7f800000);
        #pragma unroll
        for (int j = 0; j < 4; j++) {
            int p0 = t + (2*j)*FTH, p1 = t + (2*j+1)*FTH;
            pxp[j] = pk(sx[p0], sx[p1]);
            pyp[j] = pk(sy[p0], sy[p1]);
            pzp[j] = pk(sz[p0], sz[p1]);
            dist[2*j] = INF; dist[2*j+1] = INF;
        }
        int far = 0;
        for (int it = 0; it < NS; it++) {
            if (t == 0) {
                size_t o = ((size_t)b*NS + it)*3;
                out_newxyz[o] = sx[far]; out_newxyz[o+1] = sy[far]; out_newxyz[o+2] = sz[far];
                if (((it+1) & 31) == 0) { __threadfence(); atomicExch(&g_fpsprog[b], it+1); }
            }
            if (it == NS-1) break;
            float cx = sx[far], cy = sy[far], cz = sz[far];
            unsigned long long ncx = pk(-cx,-cx), ncy = pk(-cy,-cy), ncz = pk(-cz,-cz);
            #pragma unroll
            for (int j = 0; j < 4; j++) {
                unsigned long long dx = add2(pxp[j], ncx);
                unsigned long long dy = add2(pyp[j], ncy);
                unsigned long long dz = add2(pzp[j], ncz);
                unsigned long long d2 = add2(add2(mul2(dx,dx), mul2(dy,dy)), mul2(dz,dz));
                float d0, d1; upk(d2, d0, d1);
                dist[2*j]   = fminf(dist[2*j],   d0);
                dist[2*j+1] = fminf(dist[2*j+1], d1);
            }
            float m0 = fmaxf(dist[0], dist[1]), m1 = fmaxf(dist[2], dist[3]);
            float m2 = fmaxf(dist[4], dist[5]), m3 = fmaxf(dist[6], dist[7]);
            float best = fmaxf(fmaxf(m0, m1), fmaxf(m2, m3));
            unsigned inv = 0u;
            #pragma unroll
            for (int k = 0; k < 8; k++) {
                unsigned cand = 0xFFFFFFFFu - (unsigned)(t + k*FTH);
                if (dist[k] == best && cand > inv) inv = cand;
            }
            unsigned hi  = __float_as_uint(best);
            unsigned whi = redux_umax(hi);
            unsigned lo  = (hi == whi) ? inv : 0u;
            unsigned wlo = redux_umax(lo);
            int buf = (it & 1) << 4;
            if (lane == 0) { swhi[buf + w] = whi; swlo[buf + w] = wlo; }
            __syncthreads();
            unsigned h2 = swhi[buf + (lane & 15)];
            unsigned l2 = swlo[buf + (lane & 15)];
            unsigned mh = redux_umax(h2);
            unsigned ml = redux_umax((h2 == mh) ? l2 : 0u);
            far = (int)(0xFFFFFFFFu - ml);
        }

    } else if (bid < 528) {
        int idx = bid - 16;
        int b = idx >> 5, n0 = (idx & 31) * 128;
        float* Pts = dsm;
        float* Wt  = dsm + 64*128;
        for (int i = t; i < 64*64; i += FTH) { int o = i>>6, c = i&63; Wt[c*64 + o] = w0[o*67 + 3 + c]; }
        const float* pb = points + (size_t)b*64*NPT;
        for (int i = t; i < 64*128/4; i += FTH) {
            int e = i*4, c = e>>7, n = e&127;
            *(float4*)&Pts[c*128 + n] = *(const float4*)(pb + (size_t)c*NPT + n0 + n);
        }
        __syncthreads();
        int cg = t & 15, rg = t >> 4;
        unsigned long long acc[4][2];
        #pragma unroll
        for (int i = 0; i < 4; i++) { acc[i][0]=0ull; acc[i][1]=0ull; }
        #pragma unroll 4
        for (int c = 0; c < 64; c++) {
            ulonglong2 wv = *(const ulonglong2*)&Wt[c*64 + cg*4];
            #pragma unroll
            for (int i = 0; i < 4; i++) {
                float a = Pts[c*128 + rg*4 + i];
                unsigned long long aa = pk(a, a);
                acc[i][0] = ffma2(aa, wv.x, acc[i][0]);
                acc[i][1] = ffma2(aa, wv.y, acc[i][1]);
            }
        }
        float* outp = g_pprime + ((size_t)b*NPT + n0)*64;
        #pragma unroll
        for (int i = 0; i < 4; i++) {
            float4 v; upk(acc[i][0], v.x, v.y); upk(acc[i][1], v.z, v.w);
            *(float4*)(outp + (size_t)(rg*4+i)*64 + cg*4) = v;
        }
        __threadfence();
        __syncthreads();
        if (t == 0) atomicAdd(&g_ppcnt[b], 1);

    } else if (bid < 1040) {
        int idx = bid - 528;
        int b = idx >> 5, sb = idx & 31;
        float* sx = dsm; float* sy = dsm + NPT; float* sz = dsm + 2*NPT; float* spp = dsm + 3*NPT;
        int w = t>>5, lane = t&31;
        const float* p = xyz + (size_t)b*NPT*3;
        for (int i = t; i < NPT; i += FTH) {
            float px = p[3*i], py = p[3*i+1], pz = p[3*i+2];
            sx[i]=px; sy[i]=py; sz[i]=pz;
            spp[i] = __fadd_rn(__fadd_rn(__fmul_rn(px,px), __fmul_rn(py,py)), __fmul_rn(pz,pz));
        }
        if (t == 0) { spin_until(&g_fpsprog[b], (sb+1)*32); __threadfence(); }
        __syncthreads();
        const float* newxyz = out_newxyz;
        for (int q = 0; q < 2; q++) {
            int s = sb*32 + w*2 + q;
            const float* nc = newxyz + ((size_t)b*NS + s)*3;
            float cx = nc[0], cy = nc[1], cz = nc[2];
            float cc = __fadd_rn(__fadd_rn(__fmul_rn(cx,cx), __fmul_rn(cy,cy)), __fmul_rn(cz,cz));
            int count = 0, first = 0;
            int* go = g_gidx + ((size_t)b*NS + s)*NK;
            for (int base = 0; base < NPT && count < NK; base += 32) {
                int pi = base + lane;
                float px = sx[pi], py = sy[pi], pz = sz[pi];
                float pp  = spp[pi];
                float dot = __fadd_rn(__fadd_rn(__fmul_rn(cx,px), __fmul_rn(cy,py)), __fmul_rn(cz,pz));
                float sqr = __fadd_rn(__fadd_rn(cc, pp), -__fmul_rn(2.0f, dot));
                bool in = (sqr <= 0.04f);
                unsigned mask = __ballot_sync(0xffffffffu, in);
                if (count == 0 && mask) first = base + __ffs(mask) - 1;
                if (in) {
                    int pos = count + __popc(mask & ((1u << lane) - 1u));
                    if (pos < NK) go[pos] = pi;
                }
                count += __popc(mask);
            }
            if (count < NK && lane >= count) go[lane] = first;
        }
        __threadfence();
        __syncthreads();
        if (t == 0) atomicExch(&g_bqdone[b*32 + sb], 1);

    } else {
        int idx = bid - 1040;
        int b = idx >> 5, sb = idx & 31;
        float* wx = dsm; float* wy = dsm + 64; float* wz = dsm + 128;
        float* ssum = dsm + 192;
        float* ssq  = dsm + 192 + 512;
        if (t < 64) { wx[t]=w0[t*67]; wy[t]=w0[t*67+1]; wz[t]=w0[t*67+2]; }
        if (t == 0) {
            spin_until(&g_bqdone[b*32 + sb], 1);
            spin_until(&g_ppcnt[b], 32);
            __threadfence();
        }
        __syncthreads();
        int c = t & 63, rl = t >> 6;
        float wxc = wx[c], wyc = wy[c], wzc = wz[c];
        float s = 0.f, q = 0.f;
        size_t base = (size_t)b * (MROWS/NB) + (size_t)sb * 1024;
        const float* newxyz = out_newxyz;
        for (int i = 0; i < 128; i++) {
            size_t row = base + i*8 + rl;
            int g = g_gidx[row];
            int ss = (int)((row >> 5) & 1023);
            const float* nc = newxyz + ((size_t)b*NS + ss)*3;
            const float* pt = xyz + ((size_t)b*NPT + g)*3;
            float gx = pt[0]-nc[0], gy = pt[1]-nc[1], gz = pt[2]-nc[2];
            float v = g_pprime[((size_t)b*NPT + g)*64 + c];
            v = fmaf(wxc, gx, fmaf(wyc, gy, fmaf(wzc, gz, v)));
            s += v; q = fmaf(v, v, q);
        }
        ssum[rl*64 + c] = s; ssq[rl*64 + c] = q;
        __syncthreads();
        if (t < 64) {
            double S = 0.0, Q = 0.0;
            #pragma unroll
            for (int r = 0; r < 8; r++) { S += (double)ssum[r*64 + t]; Q += (double)ssq[r*64 + t]; }
            atomicAdd(&g_stat[t], S);
            atomicAdd(&g_stat[64 + t], Q);
        }
    }
}

__global__ void finalize_kernel(int C, int statOff, int bnOff,
                                const float* __restrict__ g, const float* __restrict__ bb) {
    int c = threadIdx.x;
    if (c >= C) return;
    double inv = 1.0 / (double)MROWS;
    double mean = g_stat[statOff + c] * inv;
    double var  = g_stat[statOff + C + c] * inv - mean*mean;
    double sc = (double)g[c] / sqrt(var + 1e-5);
    g_scale[bnOff + c] = (float)sc;
    g_shift[bnOff + c] = (float)((double)bb[c] - mean * sc);
}

// ---- TC GEMM v6: 128-row tiles, 256 threads, 16 rows/warp, 3 blocks/SM ----
template<int COUT>
__global__ void __launch_bounds__(256, 3) gemm_tc_kernel(const float* __restrict__ W,
                                                      const float* __restrict__ w0,
                                                      const float* __restrict__ xyz,
                                                      const float* __restrict__ newxyz) {
    constexpr int XSP = 36;
    constexpr int WSP = 72;
    constexpr int NH  = COUT / 64;
    constexpr int statOff = (COUT == 64) ? 128 : 256;
    extern __shared__ float sm[];
    unsigned* Xhi   = (unsigned*)sm;                  // [128][36]
    unsigned* Xlo   = Xhi + 128*XSP;
    unsigned* Whi   = Xlo + 128*XSP;                  // [32][72]
    unsigned* Wlo   = Whi + 32*WSP;
    float*    sstat = (float*)(Wlo + 32*WSP);         // [2*COUT]
    float*    aux   = sstat + 2*COUT;
    int t = threadIdx.x;
    size_t row0 = (size_t)blockIdx.x * 128;

    for (int i = t; i < 2*COUT; i += 256) sstat[i] = 0.f;

    if (COUT == 64) {
        if (t < 64) {
            aux[t]     = w0[t*67];   aux[64+t]  = w0[t*67+1]; aux[128+t] = w0[t*67+2];
            aux[192+t] = g_scale[t]; aux[256+t] = g_shift[t];
        }
        __syncthreads();
        int r = t >> 1, half = t & 1;
        size_t row = row0 + r;
        int g = g_gidx[row];
        int ss = (int)((row >> 5) & 1023), b = (int)(row >> 15);
        const float* nc = newxyz + ((size_t)b*NS + ss)*3;
        const float* pt = xyz + ((size_t)b*NPT + g)*3;
        float gx = pt[0]-nc[0], gy = pt[1]-nc[1], gz = pt[2]-nc[2];
        const float4* pr = (const float4*)(g_pprime + ((size_t)b*NPT + g)*64 + half*32);
        #pragma unroll
        for (int qq = 0; qq < 8; qq++) {
            float4 v = pr[qq]; int c = half*32 + qq*4;
            float z0 = fmaf(aux[c  ], gx, fmaf(aux[64+c  ], gy, fmaf(aux[128+c  ], gz, v.x)));
            float z1 = fmaf(aux[c+1], gx, fmaf(aux[64+c+1], gy, fmaf(aux[128+c+1], gz, v.y)));
            float z2 = fmaf(aux[c+2], gx, fmaf(aux[64+c+2], gy, fmaf(aux[128+c+2], gz, v.z)));
            float z3 = fmaf(aux[c+3], gx, fmaf(aux[64+c+3], gy, fmaf(aux[128+c+3], gz, v.w)));
            float v0 = fmaxf(fmaf(z0, aux[192+c  ], aux[256+c  ]), 0.f);
            float v1 = fmaxf(fmaf(z1, aux[192+c+1], aux[256+c+1]), 0.f);
            float v2 = fmaxf(fmaf(z2, aux[192+c+2], aux[256+c+2]), 0.f);
            float v3 = fmaxf(fmaf(z3, aux[192+c+3], aux[256+c+3]), 0.f);
            unsigned ph0 = pack_bf16x2(v0, v1);
            unsigned ph1 = pack_bf16x2(v2, v3);
            unsigned pl0 = pack_bf16x2(v0 - bf16lo_f32(ph0), v1 - bf16hi_f32(ph0));
            unsigned pl1 = pack_bf16x2(v2 - bf16lo_f32(ph1), v3 - bf16hi_f32(ph1));
            int kp = c >> 1;
            *(uint2*)(Xhi + (size_t)r*XSP + kp) = make_uint2(ph0, ph1);
            *(uint2*)(Xlo + (size_t)r*XSP + kp) = make_uint2(pl0, pl1);
        }
    } else {
        int c0 = (t*4) & 63;
        float s0=g_scale[64+c0], s1=g_scale[64+c0+1], s2=g_scale[64+c0+2], s3=g_scale[64+c0+3];
        float h0=g_shift[64+c0], h1=g_shift[64+c0+1], h2=g_shift[64+c0+2], h3=g_shift[64+c0+3];
        #pragma unroll
        for (int j = 0; j < 8; j++) {
            int e = t*4 + j*1024;
            float4 v = *(const float4*)(g_zB + row0*64 + e);
            int r = e >> 6;
            float v0 = fmaxf(fmaf(v.x, s0, h0), 0.f);
            float v1 = fmaxf(fmaf(v.y, s1, h1), 0.f);
            float v2 = fmaxf(fmaf(v.z, s2, h2), 0.f);
            float v3 = fmaxf(fmaf(v.w, s3, h3), 0.f);
            unsigned ph0 = pack_bf16x2(v0, v1);
            unsigned ph1 = pack_bf16x2(v2, v3);
            unsigned pl0 = pack_bf16x2(v0 - bf16lo_f32(ph0), v1 - bf16hi_f32(ph0));
            unsigned pl1 = pack_bf16x2(v2 - bf16lo_f32(ph1), v3 - bf16hi_f32(ph1));
            int kp = c0 >> 1;
            *(uint2*)(Xhi + (size_t)r*XSP + kp) = make_uint2(ph0, ph1);
            *(uint2*)(Xlo + (size_t)r*XSP + kp) = make_uint2(pl0, pl1);
        }
    }

    int w = t >> 5, lane = t & 31;
    int g = lane >> 2, tig = lane & 3;
    int rbase = w*16 + g;

    #pragma unroll
    for (int nh = 0; nh < NH; nh++) {
        __syncthreads();
        for (int i = t; i < 64*32; i += 256) {
            int n = i >> 5, kp = i & 31;
            float2 wv = *(const float2*)(W + (size_t)(nh*64 + n)*64 + 2*kp);
            unsigned ph = pack_bf16x2(wv.x, wv.y);
            unsigned pl = pack_bf16x2(wv.x - bf16lo_f32(ph), wv.y - bf16hi_f32(ph));
            Whi[kp*WSP + n] = ph;
            Wlo[kp*WSP + n] = pl;
        }
        __syncthreads();

        float acc0[8][4];
        #pragma unroll
        for (int nt = 0; nt < 8; nt++) {
            acc0[nt][0]=0.f; acc0[nt][1]=0.f; acc0[nt][2]=0.f; acc0[nt][3]=0.f;
        }
        #pragma unroll
        for (int kt = 0; kt < 4; kt++) {
            int xb0 = rbase*XSP + kt*8 + tig;
            unsigned ah0[4], al0[4];
            ah0[0] = Xhi[xb0];            ah0[1] = Xhi[xb0 + 8*XSP];
            ah0[2] = Xhi[xb0 + 4];        ah0[3] = Xhi[xb0 + 8*XSP + 4];
            al0[0] = Xlo[xb0];            al0[1] = Xlo[xb0 + 8*XSP];
            al0[2] = Xlo[xb0 + 4];        al0[3] = Xlo[xb0 + 8*XSP + 4];
            int wb = (kt*8 + tig)*WSP + g;
            #pragma unroll
            for (int cch = 0; cch < 2; cch++) {
                unsigned bh[4][2], bl[4][2];
                #pragma unroll
                for (int i = 0; i < 4; i++) {
                    int nt = cch*4 + i;
                    bh[i][0] = Whi[wb + nt*8]; bh[i][1] = Whi[wb + nt*8 + 4*WSP];
                    bl[i][0] = Wlo[wb + nt*8]; bl[i][1] = Wlo[wb + nt*8 + 4*WSP];
                }
                #pragma unroll
                for (int i = 0; i < 4; i++) mma_bf16(acc0[cch*4+i], ah0, bl[i]);
                #pragma unroll
                for (int i = 0; i < 4; i++) mma_bf16(acc0[cch*4+i], al0, bh[i]);
                #pragma unroll
                for (int i = 0; i < 4; i++) mma_bf16(acc0[cch*4+i], ah0, bh[i]);
            }
        }

        if (COUT == 64) {
            float* yr = g_zB + (row0 + rbase)*(size_t)64 + 2*tig;
            #pragma unroll
            for (int nt = 0; nt < 8; nt++) {
                *(float2*)(yr + nt*8)           = make_float2(acc0[nt][0], acc0[nt][1]);
                *(float2*)(yr + 8*64 + nt*8)    = make_float2(acc0[nt][2], acc0[nt][3]);
            }
        }

        #pragma unroll
        for (int nt = 0; nt < 8; nt++) {
            int c0 = nh*64 + nt*8 + 2*tig;
            float a0=acc0[nt][0], a1=acc0[nt][1], a2=acc0[nt][2], a3=acc0[nt][3];
            float sc0 = a0 + a2, sc1 = a1 + a3;
            float qc0 = a0*a0 + a2*a2, qc1 = a1*a1 + a3*a3;
            #pragma unroll
            for (int off = 4; off <= 16; off <<= 1) {
                sc0 += __shfl_xor_sync(0xffffffffu, sc0, off);
                sc1 += __shfl_xor_sync(0xffffffffu, sc1, off);
                qc0 += __shfl_xor_sync(0xffffffffu, qc0, off);
                qc1 += __shfl_xor_sync(0xffffffffu, qc1, off);
            }
            if (g == 0) {
                atomicAdd(&sstat[c0],        sc0); atomicAdd(&sstat[c0+1],        sc1);
                atomicAdd(&sstat[COUT+c0],   qc0); atomicAdd(&sstat[COUT+c0+1],   qc1);
            }
            if (COUT == 128) {
                float m0 = fmaxf(a0, a2), m1 = fmaxf(a1, a3);
                float n0 = fminf(a0, a2), n1 = fminf(a1, a3);
                #pragma unroll
                for (int off = 4; off <= 16; off <<= 1) {
                    m0 = fmaxf(m0, __shfl_xor_sync(0xffffffffu, m0, off));
                    m1 = fmaxf(m1, __shfl_xor_sync(0xffffffffu, m1, off));
                    n0 = fminf(n0, __shfl_xor_sync(0xffffffffu, n0, off));
                    n1 = fminf(n1, __shfl_xor_sync(0xffffffffu, n1, off));
                }
                if (g == 0) {
                    // per-HALF-group extrema (16 rows per warp)
                    size_t hg = (size_t)blockIdx.x*8 + w;
                    g_gmax[hg*128 + c0] = m0; g_gmax[hg*128 + c0+1] = m1;
                    g_gmin[hg*128 + c0] = n0; g_gmin[hg*128 + c0+1] = n1;
                }
            }
        }
    }
    __syncthreads();
    for (int i = t; i < COUT; i += 256) {
        atomicAdd(&g_stat[statOff + i],        (double)sstat[i]);
        atomicAdd(&g_stat[statOff + COUT + i], (double)sstat[COUT + i]);
    }
}

// ---- final output: BN2+ReLU+max via per-half-group extrema ----
__global__ void output_kernel(float* __restrict__ out) {
    int o = threadIdx.x;
    size_t bs = blockIdx.x;
    float sc = g_scale[128 + o], sh = g_shift[128 + o];
    float mx = fmaxf(g_gmax[(2*bs)*128 + o], g_gmax[(2*bs+1)*128 + o]);
    float mn = fminf(g_gmin[(2*bs)*128 + o], g_gmin[(2*bs+1)*128 + o]);
    float v = (sc > 0.f) ? fmaf(sc, mx, sh) : fmaf(sc, mn, sh);
    int b = (int)(bs >> 10), s = (int)(bs & 1023);
    out[(size_t)NB*NS*3 + ((size_t)b*128 + o)*NS + s] = fmaxf(v, 0.f);
}

extern "C" void kernel_launch(void* const* d_in, const int* in_sizes, int n_in,
                              void* d_out, int out_size) {
    const float* xyz    = (const float*)d_in[0];
    const float* points = (const float*)d_in[1];
    const float* w0 = (const float*)d_in[2];
    const float* g0 = (const float*)d_in[3];
    const float* b0 = (const float*)d_in[4];
    const float* w1 = (const float*)d_in[5];
    const float* g1 = (const float*)d_in[6];
    const float* b1 = (const float*)d_in[7];
    const float* w2 = (const float*)d_in[8];
    const float* g2 = (const float*)d_in[9];
    const float* b2 = (const float*)d_in[10];
    float* out = (float*)d_out;

    const int FRONT_SMEM = 4*NPT*4;
    const int G64_SMEM   = (2*128*36 + 2*32*72)*4 + 2*64*4 + 320*4;   // 57088
    const int G128_SMEM  = (2*128*36 + 2*32*72)*4 + 2*128*4;          // 56320
    cudaFuncSetAttribute(front_kernel, cudaFuncAttributeMaxDynamicSharedMemorySize, FRONT_SMEM);
    cudaFuncSetAttribute(gemm_tc_kernel<64>,  cudaFuncAttributeMaxDynamicSharedMemorySize, G64_SMEM);
    cudaFuncSetAttribute(gemm_tc_kernel<128>, cudaFuncAttributeMaxDynamicSharedMemorySize, G128_SMEM);

    zero_kernel<<<1, 512>>>();
    front_kernel<<<1552, FTH, FRONT_SMEM>>>(xyz, points, w0, out);
    finalize_kernel<<<1, 128>>>(64, 0, 0, g0, b0);
    gemm_tc_kernel<64><<<MROWS/128, 256, G64_SMEM>>>(w1, w0, xyz, out);
    finalize_kernel<<<1, 128>>>(64, 128, 64, g1, b1);
    gemm_tc_kernel<128><<<MROWS/128, 256, G128_SMEM>>>(w2, nullptr, nullptr, nullptr);
    finalize_kernel<<<1, 128>>>(128, 256, 128, g2, b2);
    output_kernel<<<NB*NS, 128>>>(out);
    (void)in_sizes; (void)n_in; (void)out_size;
}

// round 15
// speedup vs baseline: 1.0921x; 1.0921x over previous
#include <cuda_runtime.h>
#include <cstddef>

#define NB 16
#define NPT 4096
#define NS 1024
#define NK 32
#define MROWS (NB*NS*NK)
#define FTH 512

__device__ __align__(16) float g_pprime[(size_t)NB*NPT*64];
__device__ int                 g_gidx[MROWS];
__device__ __align__(16) float g_zB[(size_t)MROWS*64];   // z1
__device__ __align__(16) float g_gmax[(size_t)NB*NS*128];
__device__ __align__(16) float g_gmin[(size_t)NB*NS*128];
__device__ double              g_stat[512];
__device__ float               g_scale[320];
__device__ float               g_shift[320];
__device__ int                 g_fpsprog[NB];
__device__ int                 g_bqdone[NB*32];
__device__ int                 g_ppcnt[NB];

__device__ __forceinline__ unsigned long long pk(float lo, float hi) {
    unsigned long long r;
    asm("mov.b64 %0, {%1,%2};" : "=l"(r) : "f"(lo), "f"(hi));
    return r;
}
__device__ __forceinline__ unsigned long long ffma2(unsigned long long a, unsigned long long b, unsigned long long c) {
    unsigned long long d;
    asm("fma.rn.f32x2 %0, %1, %2, %3;" : "=l"(d) : "l"(a), "l"(b), "l"(c));
    return d;
}
__device__ __forceinline__ unsigned long long add2(unsigned long long a, unsigned long long b) {
    unsigned long long d;
    asm("add.rn.f32x2 %0, %1, %2;" : "=l"(d) : "l"(a), "l"(b));
    return d;
}
__device__ __forceinline__ unsigned long long mul2(unsigned long long a, unsigned long long b) {
    unsigned long long d;
    asm("mul.rn.f32x2 %0, %1, %2;" : "=l"(d) : "l"(a), "l"(b));
    return d;
}
__device__ __forceinline__ void upk(unsigned long long v, float& lo, float& hi) {
    asm("mov.b64 {%0,%1}, %2;" : "=f"(lo), "=f"(hi) : "l"(v));
}
__device__ __forceinline__ unsigned redux_umax(unsigned v) {
    unsigned r;
    asm("redux.sync.max.u32 %0, %1, 0xffffffff;" : "=r"(r) : "r"(v));
    return r;
}
// pack (even,odd) floats into bf16x2 word: low 16 bits = even element
__device__ __forceinline__ unsigned pack_bf16x2(float even, float odd) {
    unsigned d;
    asm("cvt.rn.bf16x2.f32 %0, %1, %2;" : "=r"(d) : "f"(odd), "f"(even));
    return d;
}
__device__ __forceinline__ float bf16lo_f32(unsigned p) { return __uint_as_float(p << 16); }
__device__ __forceinline__ float bf16hi_f32(unsigned p) { return __uint_as_float(p & 0xffff0000u); }

__device__ __forceinline__ void mma_bf16(float* c, const unsigned* a, const unsigned* b) {
    asm volatile("mma.sync.aligned.m16n8k16.row.col.f32.bf16.bf16.f32 "
        "{%0,%1,%2,%3}, {%4,%5,%6,%7}, {%8,%9}, {%0,%1,%2,%3};"
        : "+f"(c[0]), "+f"(c[1]), "+f"(c[2]), "+f"(c[3])
        : "r"(a[0]), "r"(a[1]), "r"(a[2]), "r"(a[3]), "r"(b[0]), "r"(b[1]));
}
__device__ __forceinline__ void spin_until(volatile int* p, int target) {
    while (*p < target) __nanosleep(64);
}

__global__ void zero_kernel() {
    int t = threadIdx.x;
    if (t < 512) { g_stat[t] = 0.0; g_bqdone[t] = 0; }
    if (t < NB) { g_fpsprog[t] = 0; g_ppcnt[t] = 0; }
}

// =================== mega front kernel with fps progress pipelining (unchanged) ===================
__global__ void __launch_bounds__(FTH) front_kernel(const float* __restrict__ xyz,
                                                    const float* __restrict__ points,
                                                    const float* __restrict__ w0,
                                                    float* __restrict__ out_newxyz) {
    extern __shared__ float dsm[];
    int bid = blockIdx.x;
    int t = threadIdx.x;

    if (bid < 16) {
        int b = bid;
        float* sx = dsm; float* sy = dsm + NPT; float* sz = dsm + 2*NPT;
        unsigned* swhi = (unsigned*)(dsm + 3*NPT);
        unsigned* swlo = swhi + 32;
        int w = t >> 5, lane = t & 31;
        const float* p = xyz + (size_t)b*NPT*3;
        for (int i = t; i < NPT; i += FTH) { sx[i]=p[3*i]; sy[i]=p[3*i+1]; sz[i]=p[3*i+2]; }
        __syncthreads();
        unsigned long long pxp[4], pyp[4], pzp[4];
        float dist[8];
        const float INF = __int_as_float(0x7f800000);
        #pragma unroll
        for (int j = 0; j < 4; j++) {
            int p0 = t + (2*j)*FTH, p1 = t + (2*j+1)*FTH;
            pxp[j] = pk(sx[p0], sx[p1]);
            pyp[j] = pk(sy[p0], sy[p1]);
            pzp[j] = pk(sz[p0], sz[p1]);
            dist[2*j] = INF; dist[2*j+1] = INF;
        }
        int far = 0;
        for (int it = 0; it < NS; it++) {
            if (t == 0) {
                size_t o = ((size_t)b*NS + it)*3;
                out_newxyz[o] = sx[far]; out_newxyz[o+1] = sy[far]; out_newxyz[o+2] = sz[far];
                if (((it+1) & 31) == 0) { __threadfence(); atomicExch(&g_fpsprog[b], it+1); }
            }
            if (it == NS-1) break;
            float cx = sx[far], cy = sy[far], cz = sz[far];
            unsigned long long ncx = pk(-cx,-cx), ncy = pk(-cy,-cy), ncz = pk(-cz,-cz);
            #pragma unroll
            for (int j = 0; j < 4; j++) {
                unsigned long long dx = add2(pxp[j], ncx);
                unsigned long long dy = add2(pyp[j], ncy);
                unsigned long long dz = add2(pzp[j], ncz);
                unsigned long long d2 = add2(add2(mul2(dx,dx), mul2(dy,dy)), mul2(dz,dz));
                float d0, d1; upk(d2, d0, d1);
                dist[2*j]   = fminf(dist[2*j],   d0);
                dist[2*j+1] = fminf(dist[2*j+1], d1);
            }
            float m0 = fmaxf(dist[0], dist[1]), m1 = fmaxf(dist[2], dist[3]);
            float m2 = fmaxf(dist[4], dist[5]), m3 = fmaxf(dist[6], dist[7]);
            float best = fmaxf(fmaxf(m0, m1), fmaxf(m2, m3));
            unsigned inv = 0u;
            #pragma unroll
            for (int k = 0; k < 8; k++) {
                unsigned cand = 0xFFFFFFFFu - (unsigned)(t + k*FTH);
                if (dist[k] == best && cand > inv) inv = cand;
            }
            unsigned hi  = __float_as_uint(best);
            unsigned whi = redux_umax(hi);
            unsigned lo  = (hi == whi) ? inv : 0u;
            unsigned wlo = redux_umax(lo);
            int buf = (it & 1) << 4;
            if (lane == 0) { swhi[buf + w] = whi; swlo[buf + w] = wlo; }
            __syncthreads();
            unsigned h2 = swhi[buf + (lane & 15)];
            unsigned l2 = swlo[buf + (lane & 15)];
            unsigned mh = redux_umax(h2);
            unsigned ml = redux_umax((h2 == mh) ? l2 : 0u);
            far = (int)(0xFFFFFFFFu - ml);
        }

    } else if (bid < 528) {
        int idx = bid - 16;
        int b = idx >> 5, n0 = (idx & 31) * 128;
        float* Pts = dsm;
        float* Wt  = dsm + 64*128;
        for (int i = t; i < 64*64; i += FTH) { int o = i>>6, c = i&63; Wt[c*64 + o] = w0[o*67 + 3 + c]; }
        const float* pb = points + (size_t)b*64*NPT;
        for (int i = t; i < 64*128/4; i += FTH) {
            int e = i*4, c = e>>7, n = e&127;
            *(float4*)&Pts[c*128 + n] = *(const float4*)(pb + (size_t)c*NPT + n0 + n);
        }
        __syncthreads();
        int cg = t & 15, rg = t >> 4;
        unsigned long long acc[4][2];
        #pragma unroll
        for (int i = 0; i < 4; i++) { acc[i][0]=0ull; acc[i][1]=0ull; }
        #pragma unroll 4
        for (int c = 0; c < 64; c++) {
            ulonglong2 wv = *(const ulonglong2*)&Wt[c*64 + cg*4];
            #pragma unroll
            for (int i = 0; i < 4; i++) {
                float a = Pts[c*128 + rg*4 + i];
                unsigned long long aa = pk(a, a);
                acc[i][0] = ffma2(aa, wv.x, acc[i][0]);
                acc[i][1] = ffma2(aa, wv.y, acc[i][1]);
            }
        }
        float* outp = g_pprime + ((size_t)b*NPT + n0)*64;
        #pragma unroll
        for (int i = 0; i < 4; i++) {
            float4 v; upk(acc[i][0], v.x, v.y); upk(acc[i][1], v.z, v.w);
            *(float4*)(outp + (size_t)(rg*4+i)*64 + cg*4) = v;
        }
        __threadfence();
        __syncthreads();
        if (t == 0) atomicAdd(&g_ppcnt[b], 1);

    } else if (bid < 1040) {
        int idx = bid - 528;
        int b = idx >> 5, sb = idx & 31;
        float* sx = dsm; float* sy = dsm + NPT; float* sz = dsm + 2*NPT; float* spp = dsm + 3*NPT;
        int w = t>>5, lane = t&31;
        const float* p = xyz + (size_t)b*NPT*3;
        for (int i = t; i < NPT; i += FTH) {
            float px = p[3*i], py = p[3*i+1], pz = p[3*i+2];
            sx[i]=px; sy[i]=py; sz[i]=pz;
            spp[i] = __fadd_rn(__fadd_rn(__fmul_rn(px,px), __fmul_rn(py,py)), __fmul_rn(pz,pz));
        }
        if (t == 0) { spin_until(&g_fpsprog[b], (sb+1)*32); __threadfence(); }
        __syncthreads();
        const float* newxyz = out_newxyz;
        for (int q = 0; q < 2; q++) {
            int s = sb*32 + w*2 + q;
            const float* nc = newxyz + ((size_t)b*NS + s)*3;
            float cx = nc[0], cy = nc[1], cz = nc[2];
            float cc = __fadd_rn(__fadd_rn(__fmul_rn(cx,cx), __fmul_rn(cy,cy)), __fmul_rn(cz,cz));
            int count = 0, first = 0;
            int* go = g_gidx + ((size_t)b*NS + s)*NK;
            for (int base = 0; base < NPT && count < NK; base += 32) {
                int pi = base + lane;
                float px = sx[pi], py = sy[pi], pz = sz[pi];
                float pp  = spp[pi];
                float dot = __fadd_rn(__fadd_rn(__fmul_rn(cx,px), __fmul_rn(cy,py)), __fmul_rn(cz,pz));
                float sqr = __fadd_rn(__fadd_rn(cc, pp), -__fmul_rn(2.0f, dot));
                bool in = (sqr <= 0.04f);
                unsigned mask = __ballot_sync(0xffffffffu, in);
                if (count == 0 && mask) first = base + __ffs(mask) - 1;
                if (in) {
                    int pos = count + __popc(mask & ((1u << lane) - 1u));
                    if (pos < NK) go[pos] = pi;
                }
                count += __popc(mask);
            }
            if (count < NK && lane >= count) go[lane] = first;
        }
        __threadfence();
        __syncthreads();
        if (t == 0) atomicExch(&g_bqdone[b*32 + sb], 1);

    } else {
        int idx = bid - 1040;
        int b = idx >> 5, sb = idx & 31;
        float* wx = dsm; float* wy = dsm + 64; float* wz = dsm + 128;
        float* ssum = dsm + 192;
        float* ssq  = dsm + 192 + 512;
        if (t < 64) { wx[t]=w0[t*67]; wy[t]=w0[t*67+1]; wz[t]=w0[t*67+2]; }
        if (t == 0) {
            spin_until(&g_bqdone[b*32 + sb], 1);
            spin_until(&g_ppcnt[b], 32);
            __threadfence();
        }
        __syncthreads();
        int c = t & 63, rl = t >> 6;
        float wxc = wx[c], wyc = wy[c], wzc = wz[c];
        float s = 0.f, q = 0.f;
        size_t base = (size_t)b * (MROWS/NB) + (size_t)sb * 1024;
        const float* newxyz = out_newxyz;
        for (int i = 0; i < 128; i++) {
            size_t row = base + i*8 + rl;
            int g = g_gidx[row];
            int ss = (int)((row >> 5) & 1023);
            const float* nc = newxyz + ((size_t)b*NS + ss)*3;
            const float* pt = xyz + ((size_t)b*NPT + g)*3;
            float gx = pt[0]-nc[0], gy = pt[1]-nc[1], gz = pt[2]-nc[2];
            float v = g_pprime[((size_t)b*NPT + g)*64 + c];
            v = fmaf(wxc, gx, fmaf(wyc, gy, fmaf(wzc, gz, v)));
            s += v; q = fmaf(v, v, q);
        }
        ssum[rl*64 + c] = s; ssq[rl*64 + c] = q;
        __syncthreads();
        if (t < 64) {
            double S = 0.0, Q = 0.0;
            #pragma unroll
            for (int r = 0; r < 8; r++) { S += (double)ssum[r*64 + t]; Q += (double)ssq[r*64 + t]; }
            atomicAdd(&g_stat[t], S);
            atomicAdd(&g_stat[64 + t], Q);
        }
    }
}

__global__ void finalize_kernel(int C, int statOff, int bnOff,
                                const float* __restrict__ g, const float* __restrict__ bb) {
    int c = threadIdx.x;
    if (c >= C) return;
    double inv = 1.0 / (double)MROWS;
    double mean = g_stat[statOff + c] * inv;
    double var  = g_stat[statOff + C + c] * inv - mean*mean;
    double sc = (double)g[c] / sqrt(var + 1e-5);
    g_scale[bnOff + c] = (float)sc;
    g_shift[bnOff + c] = (float)((double)bb[c] - mean * sc);
}

// ---- TC GEMM v7: R13 shape (256-row tiles, 8 warps x 32 rows) + coalesced gather ----
template<int COUT>
__global__ void __launch_bounds__(256, 2) gemm_tc_kernel(const float* __restrict__ W,
                                                      const float* __restrict__ w0,
                                                      const float* __restrict__ xyz,
                                                      const float* __restrict__ newxyz) {
    constexpr int XSP = 36;
    constexpr int WSP = 72;
    constexpr int NH  = COUT / 64;
    constexpr int statOff = (COUT == 64) ? 128 : 256;
    extern __shared__ float sm[];
    unsigned* Xhi   = (unsigned*)sm;                  // [256][36]
    unsigned* Xlo   = Xhi + 256*XSP;
    unsigned* Whi   = Xlo + 256*XSP;                  // [32][72]
    unsigned* Wlo   = Whi + 32*WSP;
    float*    sstat = (float*)(Wlo + 32*WSP);         // [2*COUT]
    float*    aux   = sstat + 2*COUT;
    int t = threadIdx.x;
    size_t row0 = (size_t)blockIdx.x * 256;

    for (int i = t; i < 2*COUT; i += 256) sstat[i] = 0.f;

    if (COUT == 64) {
        if (t < 64) {
            aux[t]     = w0[t*67];   aux[64+t]  = w0[t*67+1]; aux[128+t] = w0[t*67+2];
            aux[192+t] = g_scale[t]; aux[256+t] = g_shift[t];
        }
        __syncthreads();
        // coalesced gather: 8-lane cluster per half-row (128B contiguous per cluster)
        int cl = t >> 3, l8 = t & 7;
        for (int ps = 0; ps < 16; ps++) {
            int u = ps*32 + cl;           // half-row id in [0,512)
            int r = u >> 1, half = u & 1;
            size_t row = row0 + r;
            int g = g_gidx[row];
            int ss = (int)((row >> 5) & 1023), b = (int)(row >> 15);
            const float* nc = newxyz + ((size_t)b*NS + ss)*3;
            const float* pt = xyz + ((size_t)b*NPT + g)*3;
            float gx = pt[0]-nc[0], gy = pt[1]-nc[1], gz = pt[2]-nc[2];
            float4 v = *(const float4*)(g_pprime + ((size_t)b*NPT + g)*64 + half*32 + l8*4);
            int c = half*32 + l8*4;
            float z0 = fmaf(aux[c  ], gx, fmaf(aux[64+c  ], gy, fmaf(aux[128+c  ], gz, v.x)));
            float z1 = fmaf(aux[c+1], gx, fmaf(aux[64+c+1], gy, fmaf(aux[128+c+1], gz, v.y)));
            float z2 = fmaf(aux[c+2], gx, fmaf(aux[64+c+2], gy, fmaf(aux[128+c+2], gz, v.z)));
            float z3 = fmaf(aux[c+3], gx, fmaf(aux[64+c+3], gy, fmaf(aux[128+c+3], gz, v.w)));
            float v0 = fmaxf(fmaf(z0, aux[192+c  ], aux[256+c  ]), 0.f);
            float v1 = fmaxf(fmaf(z1, aux[192+c+1], aux[256+c+1]), 0.f);
            float v2 = fmaxf(fmaf(z2, aux[192+c+2], aux[256+c+2]), 0.f);
            float v3 = fmaxf(fmaf(z3, aux[192+c+3], aux[256+c+3]), 0.f);
            unsigned ph0 = pack_bf16x2(v0, v1);
            unsigned ph1 = pack_bf16x2(v2, v3);
            unsigned pl0 = pack_bf16x2(v0 - bf16lo_f32(ph0), v1 - bf16hi_f32(ph0));
            unsigned pl1 = pack_bf16x2(v2 - bf16lo_f32(ph1), v3 - bf16hi_f32(ph1));
            int kp = c >> 1;
            *(uint2*)(Xhi + (size_t)r*XSP + kp) = make_uint2(ph0, ph1);
            *(uint2*)(Xlo + (size_t)r*XSP + kp) = make_uint2(pl0, pl1);
        }
    } else {
        int c0 = (t*4) & 63;
        float s0=g_scale[64+c0], s1=g_scale[64+c0+1], s2=g_scale[64+c0+2], s3=g_scale[64+c0+3];
        float h0=g_shift[64+c0], h1=g_shift[64+c0+1], h2=g_shift[64+c0+2], h3=g_shift[64+c0+3];
        #pragma unroll
        for (int j = 0; j < 16; j++) {
            int e = t*4 + j*1024;
            float4 v = *(const float4*)(g_zB + row0*64 + e);
            int r = e >> 6;
            float v0 = fmaxf(fmaf(v.x, s0, h0), 0.f);
            float v1 = fmaxf(fmaf(v.y, s1, h1), 0.f);
            float v2 = fmaxf(fmaf(v.z, s2, h2), 0.f);
            float v3 = fmaxf(fmaf(v.w, s3, h3), 0.f);
            unsigned ph0 = pack_bf16x2(v0, v1);
            unsigned ph1 = pack_bf16x2(v2, v3);
            unsigned pl0 = pack_bf16x2(v0 - bf16lo_f32(ph0), v1 - bf16hi_f32(ph0));
            unsigned pl1 = pack_bf16x2(v2 - bf16lo_f32(ph1), v3 - bf16hi_f32(ph1));
            int kp = c0 >> 1;
            *(uint2*)(Xhi + (size_t)r*XSP + kp) = make_uint2(ph0, ph1);
            *(uint2*)(Xlo + (size_t)r*XSP + kp) = make_uint2(pl0, pl1);
        }
    }

    int w = t >> 5, lane = t & 31;
    int g = lane >> 2, tig = lane & 3;
    int rbase = w*32 + g;

    #pragma unroll
    for (int nh = 0; nh < NH; nh++) {
        __syncthreads();
        for (int i = t; i < 64*32; i += 256) {
            int n = i >> 5, kp = i & 31;
            float2 wv = *(const float2*)(W + (size_t)(nh*64 + n)*64 + 2*kp);
            unsigned ph = pack_bf16x2(wv.x, wv.y);
            unsigned pl = pack_bf16x2(wv.x - bf16lo_f32(ph), wv.y - bf16hi_f32(ph));
            Whi[kp*WSP + n] = ph;
            Wlo[kp*WSP + n] = pl;
        }
        __syncthreads();

        float acc0[8][4], acc1[8][4];
        #pragma unroll
        for (int nt = 0; nt < 8; nt++) {
            acc0[nt][0]=0.f; acc0[nt][1]=0.f; acc0[nt][2]=0.f; acc0[nt][3]=0.f;
            acc1[nt][0]=0.f; acc1[nt][1]=0.f; acc1[nt][2]=0.f; acc1[nt][3]=0.f;
        }
        #pragma unroll
        for (int kt = 0; kt < 4; kt++) {
            int xb0 = rbase*XSP + kt*8 + tig;
            unsigned ah0[4], al0[4], ah1[4], al1[4];
            ah0[0] = Xhi[xb0];            ah0[1] = Xhi[xb0 + 8*XSP];
            ah0[2] = Xhi[xb0 + 4];        ah0[3] = Xhi[xb0 + 8*XSP + 4];
            al0[0] = Xlo[xb0];            al0[1] = Xlo[xb0 + 8*XSP];
            al0[2] = Xlo[xb0 + 4];        al0[3] = Xlo[xb0 + 8*XSP + 4];
            int xb1 = xb0 + 16*XSP;
            ah1[0] = Xhi[xb1];            ah1[1] = Xhi[xb1 + 8*XSP];
            ah1[2] = Xhi[xb1 + 4];        ah1[3] = Xhi[xb1 + 8*XSP + 4];
            al1[0] = Xlo[xb1];            al1[1] = Xlo[xb1 + 8*XSP];
            al1[2] = Xlo[xb1 + 4];        al1[3] = Xlo[xb1 + 8*XSP + 4];
            int wb = (kt*8 + tig)*WSP + g;
            #pragma unroll
            for (int cch = 0; cch < 2; cch++) {
                unsigned bh[4][2], bl[4][2];
                #pragma unroll
                for (int i = 0; i < 4; i++) {
                    int nt = cch*4 + i;
                    bh[i][0] = Whi[wb + nt*8]; bh[i][1] = Whi[wb + nt*8 + 4*WSP];
                    bl[i][0] = Wlo[wb + nt*8]; bl[i][1] = Wlo[wb + nt*8 + 4*WSP];
                }
                #pragma unroll
                for (int i = 0; i < 4; i++) {
                    mma_bf16(acc0[cch*4+i], ah0, bl[i]);
                    mma_bf16(acc1[cch*4+i], ah1, bl[i]);
                }
                #pragma unroll
                for (int i = 0; i < 4; i++) {
                    mma_bf16(acc0[cch*4+i], al0, bh[i]);
                    mma_bf16(acc1[cch*4+i], al1, bh[i]);
                }
                #pragma unroll
                for (int i = 0; i < 4; i++) {
                    mma_bf16(acc0[cch*4+i], ah0, bh[i]);
                    mma_bf16(acc1[cch*4+i], ah1, bh[i]);
                }
            }
        }

        if (COUT == 64) {
            float* yr = g_zB + (row0 + rbase)*(size_t)64 + 2*tig;
            #pragma unroll
            for (int nt = 0; nt < 8; nt++) {
                *(float2*)(yr + nt*8)           = make_float2(acc0[nt][0], acc0[nt][1]);
                *(float2*)(yr + 8*64 + nt*8)    = make_float2(acc0[nt][2], acc0[nt][3]);
                *(float2*)(yr + 16*64 + nt*8)   = make_float2(acc1[nt][0], acc1[nt][1]);
                *(float2*)(yr + 24*64 + nt*8)   = make_float2(acc1[nt][2], acc1[nt][3]);
            }
        }

        #pragma unroll
        for (int nt = 0; nt < 8; nt++) {
            int c0 = nh*64 + nt*8 + 2*tig;
            float a0=acc0[nt][0], a1=acc0[nt][1], a2=acc0[nt][2], a3=acc0[nt][3];
            float b0=acc1[nt][0], b1=acc1[nt][1], b2=acc1[nt][2], b3=acc1[nt][3];
            float sc0 = (a0 + a2) + (b0 + b2);
            float sc1 = (a1 + a3) + (b1 + b3);
            float qc0 = (a0*a0 + a2*a2) + (b0*b0 + b2*b2);
            float qc1 = (a1*a1 + a3*a3) + (b1*b1 + b3*b3);
            #pragma unroll
            for (int off = 4; off <= 16; off <<= 1) {
                sc0 += __shfl_xor_sync(0xffffffffu, sc0, off);
                sc1 += __shfl_xor_sync(0xffffffffu, sc1, off);
                qc0 += __shfl_xor_sync(0xffffffffu, qc0, off);
                qc1 += __shfl_xor_sync(0xffffffffu, qc1, off);
            }
            if (g == 0) {
                atomicAdd(&sstat[c0],        sc0); atomicAdd(&sstat[c0+1],        sc1);
                atomicAdd(&sstat[COUT+c0],   qc0); atomicAdd(&sstat[COUT+c0+1],   qc1);
            }
            if (COUT == 128) {
                float m0 = fmaxf(fmaxf(a0, a2), fmaxf(b0, b2));
                float m1 = fmaxf(fmaxf(a1, a3), fmaxf(b1, b3));
                float n0 = fminf(fminf(a0, a2), fminf(b0, b2));
                float n1 = fminf(fminf(a1, a3), fminf(b1, b3));
                #pragma unroll
                for (int off = 4; off <= 16; off <<= 1) {
                    m0 = fmaxf(m0, __shfl_xor_sync(0xffffffffu, m0, off));
                    m1 = fmaxf(m1, __shfl_xor_sync(0xffffffffu, m1, off));
                    n0 = fminf(n0, __shfl_xor_sync(0xffffffffu, n0, off));
                    n1 = fminf(n1, __shfl_xor_sync(0xffffffffu, n1, off));
                }
                if (g == 0) {
                    size_t grp = (size_t)blockIdx.x*8 + w;
                    g_gmax[grp*128 + c0] = m0; g_gmax[grp*128 + c0+1] = m1;
                    g_gmin[grp*128 + c0] = n0; g_gmin[grp*128 + c0+1] = n1;
                }
            }
        }
    }
    __syncthreads();
    for (int i = t; i < COUT; i += 256) {
        atomicAdd(&g_stat[statOff + i],        (double)sstat[i]);
        atomicAdd(&g_stat[statOff + COUT + i], (double)sstat[COUT + i]);
    }
}

// ---- final output: BN2+ReLU+max via per-group extrema ----
__global__ void output_kernel(float* __restrict__ out) {
    int o = threadIdx.x;
    size_t bs = blockIdx.x;
    float sc = g_scale[128 + o], sh = g_shift[128 + o];
    float mx = g_gmax[bs*128 + o], mn = g_gmin[bs*128 + o];
    float v = (sc > 0.f) ? fmaf(sc, mx, sh) : fmaf(sc, mn, sh);
    int b = (int)(bs >> 10), s = (int)(bs & 1023);
    out[(size_t)NB*NS*3 + ((size_t)b*128 + o)*NS + s] = fmaxf(v, 0.f);
}

extern "C" void kernel_launch(void* const* d_in, const int* in_sizes, int n_in,
                              void* d_out, int out_size) {
    const float* xyz    = (const float*)d_in[0];
    const float* points = (const float*)d_in[1];
    const float* w0 = (const float*)d_in[2];
    const float* g0 = (const float*)d_in[3];
    const float* b0 = (const float*)d_in[4];
    const float* w1 = (const float*)d_in[5];
    const float* g1 = (const float*)d_in[6];
    const float* b1 = (const float*)d_in[7];
    const float* w2 = (const float*)d_in[8];
    const float* g2 = (const float*)d_in[9];
    const float* b2 = (const float*)d_in[10];
    float* out = (float*)d_out;

    const int FRONT_SMEM = 4*NPT*4;
    const int G64_SMEM   = (2*256*36 + 2*32*72)*4 + 2*64*4 + 320*4;   // 93952
    const int G128_SMEM  = (2*256*36 + 2*32*72)*4 + 2*128*4;          // 93184
    cudaFuncSetAttribute(front_kernel, cudaFuncAttributeMaxDynamicSharedMemorySize, FRONT_SMEM);
    cudaFuncSetAttribute(gemm_tc_kernel<64>,  cudaFuncAttributeMaxDynamicSharedMemorySize, G64_SMEM);
    cudaFuncSetAttribute(gemm_tc_kernel<128>, cudaFuncAttributeMaxDynamicSharedMemorySize, G128_SMEM);

    zero_kernel<<<1, 512>>>();
    front_kernel<<<1552, FTH, FRONT_SMEM>>>(xyz, points, w0, out);
    finalize_kernel<<<1, 128>>>(64, 0, 0, g0, b0);
    gemm_tc_kernel<64><<<MROWS/256, 256, G64_SMEM>>>(w1, w0, xyz, out);
    finalize_kernel<<<1, 128>>>(64, 128, 64, g1, b1);
    gemm_tc_kernel<128><<<MROWS/256, 256, G128_SMEM>>>(w2, nullptr, nullptr, nullptr);
    finalize_kernel<<<1, 128>>>(128, 256, 128, g2, b2);
    output_kernel<<<NB*NS, 128>>>(out);
    (void)in_sizes; (void)n_in; (void)out_size;
}

// round 16
// speedup vs baseline: 1.1945x; 1.0937x over previous
#include <cuda_runtime.h>
#include <cstddef>

#define NB 16
#define NPT 4096
#define NS 1024
#define NK 32
#define MROWS (NB*NS*NK)
#define FTH 1024

__device__ __align__(16) float g_pprime[(size_t)NB*NPT*64];
__device__ int                 g_gidx[MROWS];
__device__ __align__(16) float g_zB[(size_t)MROWS*64];   // z1
__device__ __align__(16) float g_gmax[(size_t)NB*NS*128];
__device__ __align__(16) float g_gmin[(size_t)NB*NS*128];
__device__ double              g_stat[512];
__device__ float               g_scale[320];
__device__ float               g_shift[320];
__device__ int                 g_fpsprog[NB];
__device__ int                 g_bqdone[NB*32];
__device__ int                 g_ppcnt[NB];

__device__ __forceinline__ unsigned long long pk(float lo, float hi) {
    unsigned long long r;
    asm("mov.b64 %0, {%1,%2};" : "=l"(r) : "f"(lo), "f"(hi));
    return r;
}
__device__ __forceinline__ unsigned long long ffma2(unsigned long long a, unsigned long long b, unsigned long long c) {
    unsigned long long d;
    asm("fma.rn.f32x2 %0, %1, %2, %3;" : "=l"(d) : "l"(a), "l"(b), "l"(c));
    return d;
}
__device__ __forceinline__ unsigned long long add2(unsigned long long a, unsigned long long b) {
    unsigned long long d;
    asm("add.rn.f32x2 %0, %1, %2;" : "=l"(d) : "l"(a), "l"(b));
    return d;
}
__device__ __forceinline__ unsigned long long mul2(unsigned long long a, unsigned long long b) {
    unsigned long long d;
    asm("mul.rn.f32x2 %0, %1, %2;" : "=l"(d) : "l"(a), "l"(b));
    return d;
}
__device__ __forceinline__ void upk(unsigned long long v, float& lo, float& hi) {
    asm("mov.b64 {%0,%1}, %2;" : "=f"(lo), "=f"(hi) : "l"(v));
}
__device__ __forceinline__ unsigned redux_umax(unsigned v) {
    unsigned r;
    asm("redux.sync.max.u32 %0, %1, 0xffffffff;" : "=r"(r) : "r"(v));
    return r;
}
__device__ __forceinline__ unsigned pack_bf16x2(float even, float odd) {
    unsigned d;
    asm("cvt.rn.bf16x2.f32 %0, %1, %2;" : "=r"(d) : "f"(odd), "f"(even));
    return d;
}
__device__ __forceinline__ float bf16lo_f32(unsigned p) { return __uint_as_float(p << 16); }
__device__ __forceinline__ float bf16hi_f32(unsigned p) { return __uint_as_float(p & 0xffff0000u); }

__device__ __forceinline__ void mma_bf16(float* c, const unsigned* a, const unsigned* b) {
    asm volatile("mma.sync.aligned.m16n8k16.row.col.f32.bf16.bf16.f32 "
        "{%0,%1,%2,%3}, {%4,%5,%6,%7}, {%8,%9}, {%0,%1,%2,%3};"
        : "+f"(c[0]), "+f"(c[1]), "+f"(c[2]), "+f"(c[3])
        : "r"(a[0]), "r"(a[1]), "r"(a[2]), "r"(a[3]), "r"(b[0]), "r"(b[1]));
}
__device__ __forceinline__ void spin_until(volatile int* p, int target) {
    while (*p < target) __nanosleep(64);
}

__global__ void zero_kernel() {
    int t = threadIdx.x;
    if (t < 512) { g_stat[t] = 0.0; g_bqdone[t] = 0; }
    if (t < NB) { g_fpsprog[t] = 0; g_ppcnt[t] = 0; }
}

// =================== mega front kernel, 1024 threads ===================
__global__ void __launch_bounds__(FTH) front_kernel(const float* __restrict__ xyz,
                                                    const float* __restrict__ points,
                                                    const float* __restrict__ w0,
                                                    float* __restrict__ out_newxyz) {
    extern __shared__ float dsm[];
    int bid = blockIdx.x;
    int t = threadIdx.x;

    if (bid < 16) {
        // ---- FPS v4: 1024 threads, 4 pts/thread, single-span final reduce ----
        int b = bid;
        float* sx = dsm; float* sy = dsm + NPT; float* sz = dsm + 2*NPT;
        unsigned* swhi = (unsigned*)(dsm + 3*NPT);   // [2][32]
        unsigned* swlo = swhi + 64;                  // [2][32]
        int w = t >> 5, lane = t & 31;
        const float* p = xyz + (size_t)b*NPT*3;
        for (int i = t; i < NPT; i += FTH) { sx[i]=p[3*i]; sy[i]=p[3*i+1]; sz[i]=p[3*i+2]; }
        __syncthreads();
        unsigned long long pxp[2], pyp[2], pzp[2];
        float dist[4];
        const float INF = __int_as_float(0x7f800000);
        #pragma unroll
        for (int j = 0; j < 2; j++) {
            int p0 = t + (2*j)*FTH, p1 = t + (2*j+1)*FTH;
            pxp[j] = pk(sx[p0], sx[p1]);
            pyp[j] = pk(sy[p0], sy[p1]);
            pzp[j] = pk(sz[p0], sz[p1]);
            dist[2*j] = INF; dist[2*j+1] = INF;
        }
        int far = 0;
        for (int it = 0; it < NS; it++) {
            if (t == 0) {
                size_t o = ((size_t)b*NS + it)*3;
                out_newxyz[o] = sx[far]; out_newxyz[o+1] = sy[far]; out_newxyz[o+2] = sz[far];
                if (((it+1) & 31) == 0) { __threadfence(); atomicExch(&g_fpsprog[b], it+1); }
            }
            if (it == NS-1) break;
            float cx = sx[far], cy = sy[far], cz = sz[far];
            unsigned long long ncx = pk(-cx,-cx), ncy = pk(-cy,-cy), ncz = pk(-cz,-cz);
            #pragma unroll
            for (int j = 0; j < 2; j++) {
                unsigned long long dx = add2(pxp[j], ncx);
                unsigned long long dy = add2(pyp[j], ncy);
                unsigned long long dz = add2(pzp[j], ncz);
                unsigned long long d2 = add2(add2(mul2(dx,dx), mul2(dy,dy)), mul2(dz,dz));
                float d0, d1; upk(d2, d0, d1);
                dist[2*j]   = fminf(dist[2*j],   d0);
                dist[2*j+1] = fminf(dist[2*j+1], d1);
            }
            float best = fmaxf(fmaxf(dist[0], dist[1]), fmaxf(dist[2], dist[3]));
            unsigned inv = 0u;
            #pragma unroll
            for (int k = 0; k < 4; k++) {
                unsigned cand = 0xFFFFFFFFu - (unsigned)(t + k*FTH);
                if (dist[k] == best && cand > inv) inv = cand;
            }
            unsigned hi  = __float_as_uint(best);
            unsigned whi = redux_umax(hi);
            unsigned wlo = redux_umax((hi == whi) ? inv : 0u);
            int buf = (it & 1) << 5;
            if (lane == 0) { swhi[buf + w] = whi; swlo[buf + w] = wlo; }
            __syncthreads();
            unsigned h2 = swhi[buf + lane];
            unsigned l2 = swlo[buf + lane];
            unsigned mh = redux_umax(h2);
            unsigned ml = redux_umax((h2 == mh) ? l2 : 0u);
            far = (int)(0xFFFFFFFFu - ml);
        }

    } else if (bid < 528) {
        // ---- pprime: loads with 1024 threads, compute on lower 512 ----
        int idx = bid - 16;
        int b = idx >> 5, n0 = (idx & 31) * 128;
        float* Pts = dsm;
        float* Wt  = dsm + 64*128;
        for (int i = t; i < 64*64; i += FTH) { int o = i>>6, c = i&63; Wt[c*64 + o] = w0[o*67 + 3 + c]; }
        const float* pb = points + (size_t)b*64*NPT;
        for (int i = t; i < 64*128/4; i += FTH) {
            int e = i*4, c = e>>7, n = e&127;
            *(float4*)&Pts[c*128 + n] = *(const float4*)(pb + (size_t)c*NPT + n0 + n);
        }
        __syncthreads();
        if (t < 512) {
            int cg = t & 15, rg = t >> 4;
            unsigned long long acc[4][2];
            #pragma unroll
            for (int i = 0; i < 4; i++) { acc[i][0]=0ull; acc[i][1]=0ull; }
            #pragma unroll 4
            for (int c = 0; c < 64; c++) {
                ulonglong2 wv = *(const ulonglong2*)&Wt[c*64 + cg*4];
                #pragma unroll
                for (int i = 0; i < 4; i++) {
                    float a = Pts[c*128 + rg*4 + i];
                    unsigned long long aa = pk(a, a);
                    acc[i][0] = ffma2(aa, wv.x, acc[i][0]);
                    acc[i][1] = ffma2(aa, wv.y, acc[i][1]);
                }
            }
            float* outp = g_pprime + ((size_t)b*NPT + n0)*64;
            #pragma unroll
            for (int i = 0; i < 4; i++) {
                float4 v; upk(acc[i][0], v.x, v.y); upk(acc[i][1], v.z, v.w);
                *(float4*)(outp + (size_t)(rg*4+i)*64 + cg*4) = v;
            }
        }
        __threadfence();
        __syncthreads();
        if (t == 0) atomicAdd(&g_ppcnt[b], 1);

    } else if (bid < 1040) {
        // ---- ball query: 32 warps x 1 query ----
        int idx = bid - 528;
        int b = idx >> 5, sb = idx & 31;
        float* sx = dsm; float* sy = dsm + NPT; float* sz = dsm + 2*NPT; float* spp = dsm + 3*NPT;
        int w = t>>5, lane = t&31;
        const float* p = xyz + (size_t)b*NPT*3;
        for (int i = t; i < NPT; i += FTH) {
            float px = p[3*i], py = p[3*i+1], pz = p[3*i+2];
            sx[i]=px; sy[i]=py; sz[i]=pz;
            spp[i] = __fadd_rn(__fadd_rn(__fmul_rn(px,px), __fmul_rn(py,py)), __fmul_rn(pz,pz));
        }
        if (t == 0) { spin_until(&g_fpsprog[b], (sb+1)*32); __threadfence(); }
        __syncthreads();
        const float* newxyz = out_newxyz;
        {
            int s = sb*32 + w;
            const float* nc = newxyz + ((size_t)b*NS + s)*3;
            float cx = nc[0], cy = nc[1], cz = nc[2];
            float cc = __fadd_rn(__fadd_rn(__fmul_rn(cx,cx), __fmul_rn(cy,cy)), __fmul_rn(cz,cz));
            int count = 0, first = 0;
            int* go = g_gidx + ((size_t)b*NS + s)*NK;
            for (int base = 0; base < NPT && count < NK; base += 32) {
                int pi = base + lane;
                float px = sx[pi], py = sy[pi], pz = sz[pi];
                float pp  = spp[pi];
                float dot = __fadd_rn(__fadd_rn(__fmul_rn(cx,px), __fmul_rn(cy,py)), __fmul_rn(cz,pz));
                float sqr = __fadd_rn(__fadd_rn(cc, pp), -__fmul_rn(2.0f, dot));
                bool in = (sqr <= 0.04f);
                unsigned mask = __ballot_sync(0xffffffffu, in);
                if (count == 0 && mask) first = base + __ffs(mask) - 1;
                if (in) {
                    int pos = count + __popc(mask & ((1u << lane) - 1u));
                    if (pos < NK) go[pos] = pi;
                }
                count += __popc(mask);
            }
            if (count < NK && lane >= count) go[lane] = first;
        }
        __threadfence();
        __syncthreads();
        if (t == 0) atomicExch(&g_bqdone[b*32 + sb], 1);

    } else {
        // ---- layer-0 stats: 16 row-lanes x 64 channels ----
        int idx = bid - 1040;
        int b = idx >> 5, sb = idx & 31;
        float* wx = dsm; float* wy = dsm + 64; float* wz = dsm + 128;
        float* ssum = dsm + 192;            // [16][64]
        float* ssq  = dsm + 192 + 1024;     // [16][64]
        if (t < 64) { wx[t]=w0[t*67]; wy[t]=w0[t*67+1]; wz[t]=w0[t*67+2]; }
        if (t == 0) {
            spin_until(&g_bqdone[b*32 + sb], 1);
            spin_until(&g_ppcnt[b], 32);
            __threadfence();
        }
        __syncthreads();
        int c = t & 63, rl = t >> 6;        // rl in [0,16)
        float wxc = wx[c], wyc = wy[c], wzc = wz[c];
        float s = 0.f, q = 0.f;
        size_t base = (size_t)b * (MROWS/NB) + (size_t)sb * 1024;
        const float* newxyz = out_newxyz;
        for (int i = 0; i < 64; i++) {
            size_t row = base + i*16 + rl;
            int g = g_gidx[row];
            int ss = (int)((row >> 5) & 1023);
            const float* nc = newxyz + ((size_t)b*NS + ss)*3;
            const float* pt = xyz + ((size_t)b*NPT + g)*3;
            float gx = pt[0]-nc[0], gy = pt[1]-nc[1], gz = pt[2]-nc[2];
            float v = g_pprime[((size_t)b*NPT + g)*64 + c];
            v = fmaf(wxc, gx, fmaf(wyc, gy, fmaf(wzc, gz, v)));
            s += v; q = fmaf(v, v, q);
        }
        ssum[rl*64 + c] = s; ssq[rl*64 + c] = q;
        __syncthreads();
        if (t < 64) {
            double S = 0.0, Q = 0.0;
            #pragma unroll
            for (int r = 0; r < 16; r++) { S += (double)ssum[r*64 + t]; Q += (double)ssq[r*64 + t]; }
            atomicAdd(&g_stat[t], S);
            atomicAdd(&g_stat[64 + t], Q);
        }
    }
}

__global__ void finalize_kernel(int C, int statOff, int bnOff,
                                const float* __restrict__ g, const float* __restrict__ bb) {
    int c = threadIdx.x;
    if (c >= C) return;
    double inv = 1.0 / (double)MROWS;
    double mean = g_stat[statOff + c] * inv;
    double var  = g_stat[statOff + C + c] * inv - mean*mean;
    double sc = (double)g[c] / sqrt(var + 1e-5);
    g_scale[bnOff + c] = (float)sc;
    g_shift[bnOff + c] = (float)((double)bb[c] - mean * sc);
}

// ---- TC GEMM v8: R15 + staged gidx/nc in smem ----
template<int COUT>
__global__ void __launch_bounds__(256, 2) gemm_tc_kernel(const float* __restrict__ W,
                                                      const float* __restrict__ w0,
                                                      const float* __restrict__ xyz,
                                                      const float* __restrict__ newxyz) {
    constexpr int XSP = 36;
    constexpr int WSP = 72;
    constexpr int NH  = COUT / 64;
    constexpr int statOff = (COUT == 64) ? 128 : 256;
    extern __shared__ float sm[];
    unsigned* Xhi   = (unsigned*)sm;                  // [256][36]
    unsigned* Xlo   = Xhi + 256*XSP;
    unsigned* Whi   = Xlo + 256*XSP;                  // [32][72]
    unsigned* Wlo   = Whi + 32*WSP;
    float*    sstat = (float*)(Wlo + 32*WSP);         // [2*COUT]
    float*    aux   = sstat + 2*COUT;                 // 320 floats (COUT==64)
    int*      sgidx = (int*)(aux + 320);              // 256 ints
    float*    snc   = (float*)(sgidx + 256);          // 24 floats
    int t = threadIdx.x;
    size_t row0 = (size_t)blockIdx.x * 256;

    for (int i = t; i < 2*COUT; i += 256) sstat[i] = 0.f;

    if (COUT == 64) {
        if (t < 64) {
            aux[t]     = w0[t*67];   aux[64+t]  = w0[t*67+1]; aux[128+t] = w0[t*67+2];
            aux[192+t] = g_scale[t]; aux[256+t] = g_shift[t];
        }
        sgidx[t] = g_gidx[row0 + t];
        if (t < 24) {
            int grp = t / 3, k = t % 3;
            size_t row = row0 + (size_t)grp*32;
            int ss = (int)((row >> 5) & 1023), b = (int)(row >> 15);
            snc[t] = newxyz[((size_t)b*NS + ss)*3 + k];
        }
        __syncthreads();
        int cl = t >> 3, l8 = t & 7;
        int bb = (int)(row0 >> 15);
        for (int ps = 0; ps < 16; ps++) {
            int u = ps*32 + cl;
            int r = u >> 1, half = u & 1;
            int g = sgidx[r];
            int grp = r >> 5;
            float ncx = snc[grp*3], ncy = snc[grp*3+1], ncz = snc[grp*3+2];
            const float* pt = xyz + ((size_t)bb*NPT + g)*3;
            float gx = pt[0]-ncx, gy = pt[1]-ncy, gz = pt[2]-ncz;
            float4 v = *(const float4*)(g_pprime + ((size_t)bb*NPT + g)*64 + half*32 + l8*4);
            int c = half*32 + l8*4;
            float z0 = fmaf(aux[c  ], gx, fmaf(aux[64+c  ], gy, fmaf(aux[128+c  ], gz, v.x)));
            float z1 = fmaf(aux[c+1], gx, fmaf(aux[64+c+1], gy, fmaf(aux[128+c+1], gz, v.y)));
            float z2 = fmaf(aux[c+2], gx, fmaf(aux[64+c+2], gy, fmaf(aux[128+c+2], gz, v.z)));
            float z3 = fmaf(aux[c+3], gx, fmaf(aux[64+c+3], gy, fmaf(aux[128+c+3], gz, v.w)));
            float v0 = fmaxf(fmaf(z0, aux[192+c  ], aux[256+c  ]), 0.f);
            float v1 = fmaxf(fmaf(z1, aux[192+c+1], aux[256+c+1]), 0.f);
            float v2 = fmaxf(fmaf(z2, aux[192+c+2], aux[256+c+2]), 0.f);
            float v3 = fmaxf(fmaf(z3, aux[192+c+3], aux[256+c+3]), 0.f);
            unsigned ph0 = pack_bf16x2(v0, v1);
            unsigned ph1 = pack_bf16x2(v2, v3);
            unsigned pl0 = pack_bf16x2(v0 - bf16lo_f32(ph0), v1 - bf16hi_f32(ph0));
            unsigned pl1 = pack_bf16x2(v2 - bf16lo_f32(ph1), v3 - bf16hi_f32(ph1));
            int kp = c >> 1;
            *(uint2*)(Xhi + (size_t)r*XSP + kp) = make_uint2(ph0, ph1);
            *(uint2*)(Xlo + (size_t)r*XSP + kp) = make_uint2(pl0, pl1);
        }
    } else {
        int c0 = (t*4) & 63;
        float s0=g_scale[64+c0], s1=g_scale[64+c0+1], s2=g_scale[64+c0+2], s3=g_scale[64+c0+3];
        float h0=g_shift[64+c0], h1=g_shift[64+c0+1], h2=g_shift[64+c0+2], h3=g_shift[64+c0+3];
        #pragma unroll
        for (int j = 0; j < 16; j++) {
            int e = t*4 + j*1024;
            float4 v = *(const float4*)(g_zB + row0*64 + e);
            int r = e >> 6;
            float v0 = fmaxf(fmaf(v.x, s0, h0), 0.f);
            float v1 = fmaxf(fmaf(v.y, s1, h1), 0.f);
            float v2 = fmaxf(fmaf(v.z, s2, h2), 0.f);
            float v3 = fmaxf(fmaf(v.w, s3, h3), 0.f);
            unsigned ph0 = pack_bf16x2(v0, v1);
            unsigned ph1 = pack_bf16x2(v2, v3);
            unsigned pl0 = pack_bf16x2(v0 - bf16lo_f32(ph0), v1 - bf16hi_f32(ph0));
            unsigned pl1 = pack_bf16x2(v2 - bf16lo_f32(ph1), v3 - bf16hi_f32(ph1));
            int kp = c0 >> 1;
            *(uint2*)(Xhi + (size_t)r*XSP + kp) = make_uint2(ph0, ph1);
            *(uint2*)(Xlo + (size_t)r*XSP + kp) = make_uint2(pl0, pl1);
        }
    }

    int w = t >> 5, lane = t & 31;
    int g = lane >> 2, tig = lane & 3;
    int rbase = w*32 + g;

    #pragma unroll
    for (int nh = 0; nh < NH; nh++) {
        __syncthreads();
        for (int i = t; i < 64*32; i += 256) {
            int n = i >> 5, kp = i & 31;
            float2 wv = *(const float2*)(W + (size_t)(nh*64 + n)*64 + 2*kp);
            unsigned ph = pack_bf16x2(wv.x, wv.y);
            unsigned pl = pack_bf16x2(wv.x - bf16lo_f32(ph), wv.y - bf16hi_f32(ph));
            Whi[kp*WSP + n] = ph;
            Wlo[kp*WSP + n] = pl;
        }
        __syncthreads();

        float acc0[8][4], acc1[8][4];
        #pragma unroll
        for (int nt = 0; nt < 8; nt++) {
            acc0[nt][0]=0.f; acc0[nt][1]=0.f; acc0[nt][2]=0.f; acc0[nt][3]=0.f;
            acc1[nt][0]=0.f; acc1[nt][1]=0.f; acc1[nt][2]=0.f; acc1[nt][3]=0.f;
        }
        #pragma unroll
        for (int kt = 0; kt < 4; kt++) {
            int xb0 = rbase*XSP + kt*8 + tig;
            unsigned ah0[4], al0[4], ah1[4], al1[4];
            ah0[0] = Xhi[xb0];            ah0[1] = Xhi[xb0 + 8*XSP];
            ah0[2] = Xhi[xb0 + 4];        ah0[3] = Xhi[xb0 + 8*XSP + 4];
            al0[0] = Xlo[xb0];            al0[1] = Xlo[xb0 + 8*XSP];
            al0[2] = Xlo[xb0 + 4];        al0[3] = Xlo[xb0 + 8*XSP + 4];
            int xb1 = xb0 + 16*XSP;
            ah1[0] = Xhi[xb1];            ah1[1] = Xhi[xb1 + 8*XSP];
            ah1[2] = Xhi[xb1 + 4];        ah1[3] = Xhi[xb1 + 8*XSP + 4];
            al1[0] = Xlo[xb1];            al1[1] = Xlo[xb1 + 8*XSP];
            al1[2] = Xlo[xb1 + 4];        al1[3] = Xlo[xb1 + 8*XSP + 4];
            int wb = (kt*8 + tig)*WSP + g;
            #pragma unroll
            for (int cch = 0; cch < 2; cch++) {
                unsigned bh[4][2], bl[4][2];
                #pragma unroll
                for (int i = 0; i < 4; i++) {
                    int nt = cch*4 + i;
                    bh[i][0] = Whi[wb + nt*8]; bh[i][1] = Whi[wb + nt*8 + 4*WSP];
                    bl[i][0] = Wlo[wb + nt*8]; bl[i][1] = Wlo[wb + nt*8 + 4*WSP];
                }
                #pragma unroll
                for (int i = 0; i < 4; i++) {
                    mma_bf16(acc0[cch*4+i], ah0, bl[i]);
                    mma_bf16(acc1[cch*4+i], ah1, bl[i]);
                }
                #pragma unroll
                for (int i = 0; i < 4; i++) {
                    mma_bf16(acc0[cch*4+i], al0, bh[i]);
                    mma_bf16(acc1[cch*4+i], al1, bh[i]);
                }
                #pragma unroll
                for (int i = 0; i < 4; i++) {
                    mma_bf16(acc0[cch*4+i], ah0, bh[i]);
                    mma_bf16(acc1[cch*4+i], ah1, bh[i]);
                }
            }
        }

        if (COUT == 64) {
            float* yr = g_zB + (row0 + rbase)*(size_t)64 + 2*tig;
            #pragma unroll
            for (int nt = 0; nt < 8; nt++) {
                *(float2*)(yr + nt*8)           = make_float2(acc0[nt][0], acc0[nt][1]);
                *(float2*)(yr + 8*64 + nt*8)    = make_float2(acc0[nt][2], acc0[nt][3]);
                *(float2*)(yr + 16*64 + nt*8)   = make_float2(acc1[nt][0], acc1[nt][1]);
                *(float2*)(yr + 24*64 + nt*8)   = make_float2(acc1[nt][2], acc1[nt][3]);
            }
        }

        #pragma unroll
        for (int nt = 0; nt < 8; nt++) {
            int c0 = nh*64 + nt*8 + 2*tig;
            float a0=acc0[nt][0], a1=acc0[nt][1], a2=acc0[nt][2], a3=acc0[nt][3];
            float b0=acc1[nt][0], b1=acc1[nt][1], b2=acc1[nt][2], b3=acc1[nt][3];
            float sc0 = (a0 + a2) + (b0 + b2);
            float sc1 = (a1 + a3) + (b1 + b3);
            float qc0 = (a0*a0 + a2*a2) + (b0*b0 + b2*b2);
            float qc1 = (a1*a1 + a3*a3) + (b1*b1 + b3*b3);
            #pragma unroll
            for (int off = 4; off <= 16; off <<= 1) {
                sc0 += __shfl_xor_sync(0xffffffffu, sc0, off);
                sc1 += __shfl_xor_sync(0xffffffffu, sc1, off);
                qc0 += __shfl_xor_sync(0xffffffffu, qc0, off);
                qc1 += __shfl_xor_sync(0xffffffffu, qc1, off);
            }
            if (g == 0) {
                atomicAdd(&sstat[c0],        sc0); atomicAdd(&sstat[c0+1],        sc1);
                atomicAdd(&sstat[COUT+c0],   qc0); atomicAdd(&sstat[COUT+c0+1],   qc1);
            }
            if (COUT == 128) {
                float m0 = fmaxf(fmaxf(a0, a2), fmaxf(b0, b2));
                float m1 = fmaxf(fmaxf(a1, a3), fmaxf(b1, b3));
                float n0 = fminf(fminf(a0, a2), fminf(b0, b2));
                float n1 = fminf(fminf(a1, a3), fminf(b1, b3));
                #pragma unroll
                for (int off = 4; off <= 16; off <<= 1) {
                    m0 = fmaxf(m0, __shfl_xor_sync(0xffffffffu, m0, off));
                    m1 = fmaxf(m1, __shfl_xor_sync(0xffffffffu, m1, off));
                    n0 = fminf(n0, __shfl_xor_sync(0xffffffffu, n0, off));
                    n1 = fminf(n1, __shfl_xor_sync(0xffffffffu, n1, off));
                }
                if (g == 0) {
                    size_t grp = (size_t)blockIdx.x*8 + w;
                    g_gmax[grp*128 + c0] = m0; g_gmax[grp*128 + c0+1] = m1;
                    g_gmin[grp*128 + c0] = n0; g_gmin[grp*128 + c0+1] = n1;
                }
            }
        }
    }
    __syncthreads();
    for (int i = t; i < COUT; i += 256) {
        atomicAdd(&g_stat[statOff + i],        (double)sstat[i]);
        atomicAdd(&g_stat[statOff + COUT + i], (double)sstat[COUT + i]);
    }
}

// ---- final output: BN2+ReLU+max via per-group extrema ----
__global__ void output_kernel(float* __restrict__ out) {
    int o = threadIdx.x;
    size_t bs = blockIdx.x;
    float sc = g_scale[128 + o], sh = g_shift[128 + o];
    float mx = g_gmax[bs*128 + o], mn = g_gmin[bs*128 + o];
    float v = (sc > 0.f) ? fmaf(sc, mx, sh) : fmaf(sc, mn, sh);
    int b = (int)(bs >> 10), s = (int)(bs & 1023);
    out[(size_t)NB*NS*3 + ((size_t)b*128 + o)*NS + s] = fmaxf(v, 0.f);
}

extern "C" void kernel_launch(void* const* d_in, const int* in_sizes, int n_in,
                              void* d_out, int out_size) {
    const float* xyz    = (const float*)d_in[0];
    const float* points = (const float*)d_in[1];
    const float* w0 = (const float*)d_in[2];
    const float* g0 = (const float*)d_in[3];
    const float* b0 = (const float*)d_in[4];
    const float* w1 = (const float*)d_in[5];
    const float* g1 = (const float*)d_in[6];
    const float* b1 = (const float*)d_in[7];
    const float* w2 = (const float*)d_in[8];
    const float* g2 = (const float*)d_in[9];
    const float* b2 = (const float*)d_in[10];
    float* out = (float*)d_out;

    const int FRONT_SMEM = 4*NPT*4;
    const int G64_SMEM   = (2*256*36 + 2*32*72)*4 + 2*64*4 + 320*4 + 256*4 + 24*4 + 16;
    const int G128_SMEM  = (2*256*36 + 2*32*72)*4 + 2*128*4;
    cudaFuncSetAttribute(front_kernel, cudaFuncAttributeMaxDynamicSharedMemorySize, FRONT_SMEM);
    cudaFuncSetAttribute(gemm_tc_kernel<64>,  cudaFuncAttributeMaxDynamicSharedMemorySize, G64_SMEM);
    cudaFuncSetAttribute(gemm_tc_kernel<128>, cudaFuncAttributeMaxDynamicSharedMemorySize, G128_SMEM);

    zero_kernel<<<1, 512>>>();
    front_kernel<<<1552, FTH, FRONT_SMEM>>>(xyz, points, w0, out);
    finalize_kernel<<<1, 128>>>(64, 0, 0, g0, b0);
    gemm_tc_kernel<64><<<MROWS/256, 256, G64_SMEM>>>(w1, w0, xyz, out);
    finalize_kernel<<<1, 128>>>(64, 128, 64, g1, b1);
    gemm_tc_kernel<128><<<MROWS/256, 256, G128_SMEM>>>(w2, nullptr, nullptr, nullptr);
    finalize_kernel<<<1, 128>>>(128, 256, 128, g2, b2);
    output_kernel<<<NB*NS, 128>>>(out);
    (void)in_sizes; (void)n_in; (void)out_size;
}

// round 17
// speedup vs baseline: 1.2093x; 1.0124x over previous
#include <cuda_runtime.h>
#include <cstddef>

#define NB 16
#define NPT 4096
#define NS 1024
#define NK 32
#define MROWS (NB*NS*NK)
#define FTH 1024

__device__ __align__(16) float g_pprime[(size_t)NB*NPT*64];
__device__ int                 g_gidx[MROWS];
__device__ __align__(16) float g_zB[(size_t)MROWS*64];   // z1
__device__ __align__(16) float g_gmax[(size_t)NB*NS*128];
__device__ __align__(16) float g_gmin[(size_t)NB*NS*128];
__device__ double              g_stat[512];
__device__ float               g_scale[320];
__device__ float               g_shift[320];
__device__ int                 g_fpsprog[NB];
__device__ int                 g_bqdone[NB*32];
__device__ int                 g_ppcnt[NB];

__device__ __forceinline__ unsigned long long pk(float lo, float hi) {
    unsigned long long r;
    asm("mov.b64 %0, {%1,%2};" : "=l"(r) : "f"(lo), "f"(hi));
    return r;
}
__device__ __forceinline__ unsigned long long ffma2(unsigned long long a, unsigned long long b, unsigned long long c) {
    unsigned long long d;
    asm("fma.rn.f32x2 %0, %1, %2, %3;" : "=l"(d) : "l"(a), "l"(b), "l"(c));
    return d;
}
__device__ __forceinline__ unsigned long long add2(unsigned long long a, unsigned long long b) {
    unsigned long long d;
    asm("add.rn.f32x2 %0, %1, %2;" : "=l"(d) : "l"(a), "l"(b));
    return d;
}
__device__ __forceinline__ unsigned long long mul2(unsigned long long a, unsigned long long b) {
    unsigned long long d;
    asm("mul.rn.f32x2 %0, %1, %2;" : "=l"(d) : "l"(a), "l"(b));
    return d;
}
__device__ __forceinline__ void upk(unsigned long long v, float& lo, float& hi) {
    asm("mov.b64 {%0,%1}, %2;" : "=f"(lo), "=f"(hi) : "l"(v));
}
__device__ __forceinline__ unsigned redux_umax(unsigned v) {
    unsigned r;
    asm("redux.sync.max.u32 %0, %1, 0xffffffff;" : "=r"(r) : "r"(v));
    return r;
}
__device__ __forceinline__ unsigned pack_bf16x2(float even, float odd) {
    unsigned d;
    asm("cvt.rn.bf16x2.f32 %0, %1, %2;" : "=r"(d) : "f"(odd), "f"(even));
    return d;
}
__device__ __forceinline__ float bf16lo_f32(unsigned p) { return __uint_as_float(p << 16); }
__device__ __forceinline__ float bf16hi_f32(unsigned p) { return __uint_as_float(p & 0xffff0000u); }

__device__ __forceinline__ void mma_bf16(float* c, const unsigned* a, const unsigned* b) {
    asm volatile("mma.sync.aligned.m16n8k16.row.col.f32.bf16.bf16.f32 "
        "{%0,%1,%2,%3}, {%4,%5,%6,%7}, {%8,%9}, {%0,%1,%2,%3};"
        : "+f"(c[0]), "+f"(c[1]), "+f"(c[2]), "+f"(c[3])
        : "r"(a[0]), "r"(a[1]), "r"(a[2]), "r"(a[3]), "r"(b[0]), "r"(b[1]));
}
__device__ __forceinline__ void spin_until(volatile int* p, int target) {
    while (*p < target) __nanosleep(64);
}

__global__ void zero_kernel() {
    int t = threadIdx.x;
    if (t < 512) { g_stat[t] = 0.0; g_bqdone[t] = 0; }
    if (t < NB) { g_fpsprog[t] = 0; g_ppcnt[t] = 0; }
}

// =================== mega front kernel, 1024 threads ===================
__global__ void __launch_bounds__(FTH) front_kernel(const float* __restrict__ xyz,
                                                    const float* __restrict__ points,
                                                    const float* __restrict__ w0,
                                                    float* __restrict__ out_newxyz) {
    extern __shared__ float dsm[];
    int bid = blockIdx.x;
    int t = threadIdx.x;

    if (bid < 16) {
        // ---- FPS v5: float4 points, u64 packed warp keys, first-k tie-break ----
        int b = bid;
        float4* sc4 = (float4*)dsm;                              // [NPT]
        unsigned long long* skey = (unsigned long long*)(dsm + 4*NPT);  // [2][32]
        int w = t >> 5, lane = t & 31;
        const float* p = xyz + (size_t)b*NPT*3;
        for (int i = t; i < NPT; i += FTH)
            sc4[i] = make_float4(p[3*i], p[3*i+1], p[3*i+2], 0.f);
        __syncthreads();
        unsigned long long pxp[2], pyp[2], pzp[2];
        float dist[4];
        const float INF = __int_as_float(0x7f800000);
        #pragma unroll
        for (int j = 0; j < 2; j++) {
            float4 a = sc4[t + (2*j)*FTH], c = sc4[t + (2*j+1)*FTH];
            pxp[j] = pk(a.x, c.x);
            pyp[j] = pk(a.y, c.y);
            pzp[j] = pk(a.z, c.z);
            dist[2*j] = INF; dist[2*j+1] = INF;
        }
        unsigned base = 0xFFFFFFFFu - (unsigned)t;
        int far = 0;
        for (int it = 0; it < NS; it++) {
            float4 cen = sc4[far];
            if (t == 0) {
                size_t o = ((size_t)b*NS + it)*3;
                out_newxyz[o] = cen.x; out_newxyz[o+1] = cen.y; out_newxyz[o+2] = cen.z;
                if (((it+1) & 31) == 0) { __threadfence(); atomicExch(&g_fpsprog[b], it+1); }
            }
            if (it == NS-1) break;
            unsigned long long ncx = pk(-cen.x,-cen.x), ncy = pk(-cen.y,-cen.y), ncz = pk(-cen.z,-cen.z);
            #pragma unroll
            for (int j = 0; j < 2; j++) {
                unsigned long long dx = add2(pxp[j], ncx);
                unsigned long long dy = add2(pyp[j], ncy);
                unsigned long long dz = add2(pzp[j], ncz);
                unsigned long long d2 = add2(add2(mul2(dx,dx), mul2(dy,dy)), mul2(dz,dz));
                float d0, d1; upk(d2, d0, d1);
                dist[2*j]   = fminf(dist[2*j],   d0);
                dist[2*j+1] = fminf(dist[2*j+1], d1);
            }
            float best = fmaxf(fmaxf(dist[0], dist[1]), fmaxf(dist[2], dist[3]));
            // first k with dist[k]==best -> largest candidate (cands decrease in k)
            int kf = (dist[0]==best) ? 0 : ((dist[1]==best) ? 1 : ((dist[2]==best) ? 2 : 3));
            unsigned inv = base - (unsigned)(kf*FTH);
            unsigned hi  = __float_as_uint(best);
            unsigned whi = redux_umax(hi);
            unsigned wlo = redux_umax((hi == whi) ? inv : 0u);
            int buf = (it & 1) << 5;
            if (lane == 0) skey[buf + w] = ((unsigned long long)whi << 32) | wlo;
            __syncthreads();
            unsigned long long k2 = skey[buf + lane];
            unsigned h2 = (unsigned)(k2 >> 32);
            unsigned l2 = (unsigned)k2;
            unsigned mh = redux_umax(h2);
            unsigned ml = redux_umax((h2 == mh) ? l2 : 0u);
            far = (int)(0xFFFFFFFFu - ml);
        }

    } else if (bid < 528) {
        // ---- pprime: loads with 1024 threads, compute on lower 512 ----
        int idx = bid - 16;
        int b = idx >> 5, n0 = (idx & 31) * 128;
        float* Pts = dsm;
        float* Wt  = dsm + 64*128;
        for (int i = t; i < 64*64; i += FTH) { int o = i>>6, c = i&63; Wt[c*64 + o] = w0[o*67 + 3 + c]; }
        const float* pb = points + (size_t)b*64*NPT;
        for (int i = t; i < 64*128/4; i += FTH) {
            int e = i*4, c = e>>7, n = e&127;
            *(float4*)&Pts[c*128 + n] = *(const float4*)(pb + (size_t)c*NPT + n0 + n);
        }
        __syncthreads();
        if (t < 512) {
            int cg = t & 15, rg = t >> 4;
            unsigned long long acc[4][2];
            #pragma unroll
            for (int i = 0; i < 4; i++) { acc[i][0]=0ull; acc[i][1]=0ull; }
            #pragma unroll 4
            for (int c = 0; c < 64; c++) {
                ulonglong2 wv = *(const ulonglong2*)&Wt[c*64 + cg*4];
                #pragma unroll
                for (int i = 0; i < 4; i++) {
                    float a = Pts[c*128 + rg*4 + i];
                    unsigned long long aa = pk(a, a);
                    acc[i][0] = ffma2(aa, wv.x, acc[i][0]);
                    acc[i][1] = ffma2(aa, wv.y, acc[i][1]);
                }
            }
            float* outp = g_pprime + ((size_t)b*NPT + n0)*64;
            #pragma unroll
            for (int i = 0; i < 4; i++) {
                float4 v; upk(acc[i][0], v.x, v.y); upk(acc[i][1], v.z, v.w);
                *(float4*)(outp + (size_t)(rg*4+i)*64 + cg*4) = v;
            }
        }
        __threadfence();
        __syncthreads();
        if (t == 0) atomicAdd(&g_ppcnt[b], 1);

    } else if (bid < 1040) {
        // ---- ball query: 32 warps x 1 query ----
        int idx = bid - 528;
        int b = idx >> 5, sb = idx & 31;
        float* sx = dsm; float* sy = dsm + NPT; float* sz = dsm + 2*NPT; float* spp = dsm + 3*NPT;
        int w = t>>5, lane = t&31;
        const float* p = xyz + (size_t)b*NPT*3;
        for (int i = t; i < NPT; i += FTH) {
            float px = p[3*i], py = p[3*i+1], pz = p[3*i+2];
            sx[i]=px; sy[i]=py; sz[i]=pz;
            spp[i] = __fadd_rn(__fadd_rn(__fmul_rn(px,px), __fmul_rn(py,py)), __fmul_rn(pz,pz));
        }
        if (t == 0) { spin_until(&g_fpsprog[b], (sb+1)*32); __threadfence(); }
        __syncthreads();
        const float* newxyz = out_newxyz;
        {
            int s = sb*32 + w;
            const float* nc = newxyz + ((size_t)b*NS + s)*3;
            float cx = nc[0], cy = nc[1], cz = nc[2];
            float cc = __fadd_rn(__fadd_rn(__fmul_rn(cx,cx), __fmul_rn(cy,cy)), __fmul_rn(cz,cz));
            int count = 0, first = 0;
            int* go = g_gidx + ((size_t)b*NS + s)*NK;
            for (int base = 0; base < NPT && count < NK; base += 32) {
                int pi = base + lane;
                float px = sx[pi], py = sy[pi], pz = sz[pi];
                float pp  = spp[pi];
                float dot = __fadd_rn(__fadd_rn(__fmul_rn(cx,px), __fmul_rn(cy,py)), __fmul_rn(cz,pz));
                float sqr = __fadd_rn(__fadd_rn(cc, pp), -__fmul_rn(2.0f, dot));
                bool in = (sqr <= 0.04f);
                unsigned mask = __ballot_sync(0xffffffffu, in);
                if (count == 0 && mask) first = base + __ffs(mask) - 1;
                if (in) {
                    int pos = count + __popc(mask & ((1u << lane) - 1u));
                    if (pos < NK) go[pos] = pi;
                }
                count += __popc(mask);
            }
            if (count < NK && lane >= count) go[lane] = first;
        }
        __threadfence();
        __syncthreads();
        if (t == 0) atomicExch(&g_bqdone[b*32 + sb], 1);

    } else {
        // ---- layer-0 stats: 16 row-lanes x 64 channels ----
        int idx = bid - 1040;
        int b = idx >> 5, sb = idx & 31;
        float* wx = dsm; float* wy = dsm + 64; float* wz = dsm + 128;
        float* ssum = dsm + 192;            // [16][64]
        float* ssq  = dsm + 192 + 1024;     // [16][64]
        if (t < 64) { wx[t]=w0[t*67]; wy[t]=w0[t*67+1]; wz[t]=w0[t*67+2]; }
        if (t == 0) {
            spin_until(&g_bqdone[b*32 + sb], 1);
            spin_until(&g_ppcnt[b], 32);
            __threadfence();
        }
        __syncthreads();
        int c = t & 63, rl = t >> 6;
        float wxc = wx[c], wyc = wy[c], wzc = wz[c];
        float s = 0.f, q = 0.f;
        size_t base = (size_t)b * (MROWS/NB) + (size_t)sb * 1024;
        const float* newxyz = out_newxyz;
        for (int i = 0; i < 64; i++) {
            size_t row = base + i*16 + rl;
            int g = g_gidx[row];
            int ss = (int)((row >> 5) & 1023);
            const float* nc = newxyz + ((size_t)b*NS + ss)*3;
            const float* pt = xyz + ((size_t)b*NPT + g)*3;
            float gx = pt[0]-nc[0], gy = pt[1]-nc[1], gz = pt[2]-nc[2];
            float v = g_pprime[((size_t)b*NPT + g)*64 + c];
            v = fmaf(wxc, gx, fmaf(wyc, gy, fmaf(wzc, gz, v)));
            s += v; q = fmaf(v, v, q);
        }
        ssum[rl*64 + c] = s; ssq[rl*64 + c] = q;
        __syncthreads();
        if (t < 64) {
            double S = 0.0, Q = 0.0;
            #pragma unroll
            for (int r = 0; r < 16; r++) { S += (double)ssum[r*64 + t]; Q += (double)ssq[r*64 + t]; }
            atomicAdd(&g_stat[t], S);
            atomicAdd(&g_stat[64 + t], Q);
        }
    }
}

__global__ void finalize_kernel(int C, int statOff, int bnOff,
                                const float* __restrict__ g, const float* __restrict__ bb) {
    int c = threadIdx.x;
    if (c >= C) return;
    double inv = 1.0 / (double)MROWS;
    double mean = g_stat[statOff + c] * inv;
    double var  = g_stat[statOff + C + c] * inv - mean*mean;
    double sc = (double)g[c] / sqrt(var + 1e-5);
    g_scale[bnOff + c] = (float)sc;
    g_shift[bnOff + c] = (float)((double)bb[c] - mean * sc);
}

// ---- TC GEMM v9: R16 + unrolled gather for MLP ----
template<int COUT>
__global__ void __launch_bounds__(256, 2) gemm_tc_kernel(const float* __restrict__ W,
                                                      const float* __restrict__ w0,
                                                      const float* __restrict__ xyz,
                                                      const float* __restrict__ newxyz) {
    constexpr int XSP = 36;
    constexpr int WSP = 72;
    constexpr int NH  = COUT / 64;
    constexpr int statOff = (COUT == 64) ? 128 : 256;
    extern __shared__ float sm[];
    unsigned* Xhi   = (unsigned*)sm;                  // [256][36]
    unsigned* Xlo   = Xhi + 256*XSP;
    unsigned* Whi   = Xlo + 256*XSP;                  // [32][72]
    unsigned* Wlo   = Whi + 32*WSP;
    float*    sstat = (float*)(Wlo + 32*WSP);         // [2*COUT]
    float*    aux   = sstat + 2*COUT;                 // 320 floats (COUT==64)
    int*      sgidx = (int*)(aux + 320);              // 256 ints
    float*    snc   = (float*)(sgidx + 256);          // 24 floats
    int t = threadIdx.x;
    size_t row0 = (size_t)blockIdx.x * 256;

    for (int i = t; i < 2*COUT; i += 256) sstat[i] = 0.f;

    if (COUT == 64) {
        if (t < 64) {
            aux[t]     = w0[t*67];   aux[64+t]  = w0[t*67+1]; aux[128+t] = w0[t*67+2];
            aux[192+t] = g_scale[t]; aux[256+t] = g_shift[t];
        }
        sgidx[t] = g_gidx[row0 + t];
        if (t < 24) {
            int grp = t / 3, k = t % 3;
            size_t row = row0 + (size_t)grp*32;
            int ss = (int)((row >> 5) & 1023), b = (int)(row >> 15);
            snc[t] = newxyz[((size_t)b*NS + ss)*3 + k];
        }
        __syncthreads();
        int cl = t >> 3, l8 = t & 7;
        int bb = (int)(row0 >> 15);
        #pragma unroll 4
        for (int ps = 0; ps < 16; ps++) {
            int u = ps*32 + cl;
            int r = u >> 1, half = u & 1;
            int g = sgidx[r];
            int grp = r >> 5;
            float ncx = snc[grp*3], ncy = snc[grp*3+1], ncz = snc[grp*3+2];
            const float* pt = xyz + ((size_t)bb*NPT + g)*3;
            float gx = pt[0]-ncx, gy = pt[1]-ncy, gz = pt[2]-ncz;
            float4 v = *(const float4*)(g_pprime + ((size_t)bb*NPT + g)*64 + half*32 + l8*4);
            int c = half*32 + l8*4;
            float z0 = fmaf(aux[c  ], gx, fmaf(aux[64+c  ], gy, fmaf(aux[128+c  ], gz, v.x)));
            float z1 = fmaf(aux[c+1], gx, fmaf(aux[64+c+1], gy, fmaf(aux[128+c+1], gz, v.y)));
            float z2 = fmaf(aux[c+2], gx, fmaf(aux[64+c+2], gy, fmaf(aux[128+c+2], gz, v.z)));
            float z3 = fmaf(aux[c+3], gx, fmaf(aux[64+c+3], gy, fmaf(aux[128+c+3], gz, v.w)));
            float v0 = fmaxf(fmaf(z0, aux[192+c  ], aux[256+c  ]), 0.f);
            float v1 = fmaxf(fmaf(z1, aux[192+c+1], aux[256+c+1]), 0.f);
            float v2 = fmaxf(fmaf(z2, aux[192+c+2], aux[256+c+2]), 0.f);
            float v3 = fmaxf(fmaf(z3, aux[192+c+3], aux[256+c+3]), 0.f);
            unsigned ph0 = pack_bf16x2(v0, v1);
            unsigned ph1 = pack_bf16x2(v2, v3);
            unsigned pl0 = pack_bf16x2(v0 - bf16lo_f32(ph0), v1 - bf16hi_f32(ph0));
            unsigned pl1 = pack_bf16x2(v2 - bf16lo_f32(ph1), v3 - bf16hi_f32(ph1));
            int kp = c >> 1;
            *(uint2*)(Xhi + (size_t)r*XSP + kp) = make_uint2(ph0, ph1);
            *(uint2*)(Xlo + (size_t)r*XSP + kp) = make_uint2(pl0, pl1);
        }
    } else {
        int c0 = (t*4) & 63;
        float s0=g_scale[64+c0], s1=g_scale[64+c0+1], s2=g_scale[64+c0+2], s3=g_scale[64+c0+3];
        float h0=g_shift[64+c0], h1=g_shift[64+c0+1], h2=g_shift[64+c0+2], h3=g_shift[64+c0+3];
        #pragma unroll
        for (int j = 0; j < 16; j++) {
            int e = t*4 + j*1024;
            float4 v = *(const float4*)(g_zB + row0*64 + e);
            int r = e >> 6;
            float v0 = fmaxf(fmaf(v.x, s0, h0), 0.f);
            float v1 = fmaxf(fmaf(v.y, s1, h1), 0.f);
            float v2 = fmaxf(fmaf(v.z, s2, h2), 0.f);
            float v3 = fmaxf(fmaf(v.w, s3, h3), 0.f);
            unsigned ph0 = pack_bf16x2(v0, v1);
            unsigned ph1 = pack_bf16x2(v2, v3);
            unsigned pl0 = pack_bf16x2(v0 - bf16lo_f32(ph0), v1 - bf16hi_f32(ph0));
            unsigned pl1 = pack_bf16x2(v2 - bf16lo_f32(ph1), v3 - bf16hi_f32(ph1));
            int kp = c0 >> 1;
            *(uint2*)(Xhi + (size_t)r*XSP + kp) = make_uint2(ph0, ph1);
            *(uint2*)(Xlo + (size_t)r*XSP + kp) = make_uint2(pl0, pl1);
        }
    }

    int w = t >> 5, lane = t & 31;
    int g = lane >> 2, tig = lane & 3;
    int rbase = w*32 + g;

    #pragma unroll
    for (int nh = 0; nh < NH; nh++) {
        __syncthreads();
        for (int i = t; i < 64*32; i += 256) {
            int n = i >> 5, kp = i & 31;
            float2 wv = *(const float2*)(W + (size_t)(nh*64 + n)*64 + 2*kp);
            unsigned ph = pack_bf16x2(wv.x, wv.y);
            unsigned pl = pack_bf16x2(wv.x - bf16lo_f32(ph), wv.y - bf16hi_f32(ph));
            Whi[kp*WSP + n] = ph;
            Wlo[kp*WSP + n] = pl;
        }
        __syncthreads();

        float acc0[8][4], acc1[8][4];
        #pragma unroll
        for (int nt = 0; nt < 8; nt++) {
            acc0[nt][0]=0.f; acc0[nt][1]=0.f; acc0[nt][2]=0.f; acc0[nt][3]=0.f;
            acc1[nt][0]=0.f; acc1[nt][1]=0.f; acc1[nt][2]=0.f; acc1[nt][3]=0.f;
        }
        #pragma unroll
        for (int kt = 0; kt < 4; kt++) {
            int xb0 = rbase*XSP + kt*8 + tig;
            unsigned ah0[4], al0[4], ah1[4], al1[4];
            ah0[0] = Xhi[xb0];            ah0[1] = Xhi[xb0 + 8*XSP];
            ah0[2] = Xhi[xb0 + 4];        ah0[3] = Xhi[xb0 + 8*XSP + 4];
            al0[0] = Xlo[xb0];            al0[1] = Xlo[xb0 + 8*XSP];
            al0[2] = Xlo[xb0 + 4];        al0[3] = Xlo[xb0 + 8*XSP + 4];
            int xb1 = xb0 + 16*XSP;
            ah1[0] = Xhi[xb1];            ah1[1] = Xhi[xb1 + 8*XSP];
            ah1[2] = Xhi[xb1 + 4];        ah1[3] = Xhi[xb1 + 8*XSP + 4];
            al1[0] = Xlo[xb1];            al1[1] = Xlo[xb1 + 8*XSP];
            al1[2] = Xlo[xb1 + 4];        al1[3] = Xlo[xb1 + 8*XSP + 4];
            int wb = (kt*8 + tig)*WSP + g;
            #pragma unroll
            for (int cch = 0; cch < 2; cch++) {
                unsigned bh[4][2], bl[4][2];
                #pragma unroll
                for (int i = 0; i < 4; i++) {
                    int nt = cch*4 + i;
                    bh[i][0] = Whi[wb + nt*8]; bh[i][1] = Whi[wb + nt*8 + 4*WSP];
                    bl[i][0] = Wlo[wb + nt*8]; bl[i][1] = Wlo[wb + nt*8 + 4*WSP];
                }
                #pragma unroll
                for (int i = 0; i < 4; i++) {
                    mma_bf16(acc0[cch*4+i], ah0, bl[i]);
                    mma_bf16(acc1[cch*4+i], ah1, bl[i]);
                }
                #pragma unroll
                for (int i = 0; i < 4; i++) {
                    mma_bf16(acc0[cch*4+i], al0, bh[i]);
                    mma_bf16(acc1[cch*4+i], al1, bh[i]);
                }
                #pragma unroll
                for (int i = 0; i < 4; i++) {
                    mma_bf16(acc0[cch*4+i], ah0, bh[i]);
                    mma_bf16(acc1[cch*4+i], ah1, bh[i]);
                }
            }
        }

        if (COUT == 64) {
            float* yr = g_zB + (row0 + rbase)*(size_t)64 + 2*tig;
            #pragma unroll
            for (int nt = 0; nt < 8; nt++) {
                *(float2*)(yr + nt*8)           = make_float2(acc0[nt][0], acc0[nt][1]);
                *(float2*)(yr + 8*64 + nt*8)    = make_float2(acc0[nt][2], acc0[nt][3]);
                *(float2*)(yr + 16*64 + nt*8)   = make_float2(acc1[nt][0], acc1[nt][1]);
                *(float2*)(yr + 24*64 + nt*8)   = make_float2(acc1[nt][2], acc1[nt][3]);
            }
        }

        #pragma unroll
        for (int nt = 0; nt < 8; nt++) {
            int c0 = nh*64 + nt*8 + 2*tig;
            float a0=acc0[nt][0], a1=acc0[nt][1], a2=acc0[nt][2], a3=acc0[nt][3];
            float b0=acc1[nt][0], b1=acc1[nt][1], b2=acc1[nt][2], b3=acc1[nt][3];
            float sc0 = (a0 + a2) + (b0 + b2);
            float sc1 = (a1 + a3) + (b1 + b3);
            float qc0 = (a0*a0 + a2*a2) + (b0*b0 + b2*b2);
            float qc1 = (a1*a1 + a3*a3) + (b1*b1 + b3*b3);
            #pragma unroll
            for (int off = 4; off <= 16; off <<= 1) {
                sc0 += __shfl_xor_sync(0xffffffffu, sc0, off);
                sc1 += __shfl_xor_sync(0xffffffffu, sc1, off);
                qc0 += __shfl_xor_sync(0xffffffffu, qc0, off);
                qc1 += __shfl_xor_sync(0xffffffffu, qc1, off);
            }
            if (g == 0) {
                atomicAdd(&sstat[c0],        sc0); atomicAdd(&sstat[c0+1],        sc1);
                atomicAdd(&sstat[COUT+c0],   qc0); atomicAdd(&sstat[COUT+c0+1],   qc1);
            }
            if (COUT == 128) {
                float m0 = fmaxf(fmaxf(a0, a2), fmaxf(b0, b2));
                float m1 = fmaxf(fmaxf(a1, a3), fmaxf(b1, b3));
                float n0 = fminf(fminf(a0, a2), fminf(b0, b2));
                float n1 = fminf(fminf(a1, a3), fminf(b1, b3));
                #pragma unroll
                for (int off = 4; off <= 16; off <<= 1) {
                    m0 = fmaxf(m0, __shfl_xor_sync(0xffffffffu, m0, off));
                    m1 = fmaxf(m1, __shfl_xor_sync(0xffffffffu, m1, off));
                    n0 = fminf(n0, __shfl_xor_sync(0xffffffffu, n0, off));
                    n1 = fminf(n1, __shfl_xor_sync(0xffffffffu, n1, off));
                }
                if (g == 0) {
                    size_t grp = (size_t)blockIdx.x*8 + w;
                    g_gmax[grp*128 + c0] = m0; g_gmax[grp*128 + c0+1] = m1;
                    g_gmin[grp*128 + c0] = n0; g_gmin[grp*128 + c0+1] = n1;
                }
            }
        }
    }
    __syncthreads();
    for (int i = t; i < COUT; i += 256) {
        atomicAdd(&g_stat[statOff + i],        (double)sstat[i]);
        atomicAdd(&g_stat[statOff + COUT + i], (double)sstat[COUT + i]);
    }
}

// ---- final output: BN2+ReLU+max via per-group extrema ----
__global__ void output_kernel(float* __restrict__ out) {
    int o = threadIdx.x;
    size_t bs = blockIdx.x;
    float sc = g_scale[128 + o], sh = g_shift[128 + o];
    float mx = g_gmax[bs*128 + o], mn = g_gmin[bs*128 + o];
    float v = (sc > 0.f) ? fmaf(sc, mx, sh) : fmaf(sc, mn, sh);
    int b = (int)(bs >> 10), s = (int)(bs & 1023);
    out[(size_t)NB*NS*3 + ((size_t)b*128 + o)*NS + s] = fmaxf(v, 0.f);
}

extern "C" void kernel_launch(void* const* d_in, const int* in_sizes, int n_in,
                              void* d_out, int out_size) {
    const float* xyz    = (const float*)d_in[0];
    const float* points = (const float*)d_in[1];
    const float* w0 = (const float*)d_in[2];
    const float* g0 = (const float*)d_in[3];
    const float* b0 = (const float*)d_in[4];
    const float* w1 = (const float*)d_in[5];
    const float* g1 = (const float*)d_in[6];
    const float* b1 = (const float*)d_in[7];
    const float* w2 = (const float*)d_in[8];
    const float* g2 = (const float*)d_in[9];
    const float* b2 = (const float*)d_in[10];
    float* out = (float*)d_out;

    const int FRONT_SMEM = 4*NPT*4 + 2*32*8;   // 66048
    const int G64_SMEM   = (2*256*36 + 2*32*72)*4 + 2*64*4 + 320*4 + 256*4 + 24*4 + 16;
    const int G128_SMEM  = (2*256*36 + 2*32*72)*4 + 2*128*4;
    cudaFuncSetAttribute(front_kernel, cudaFuncAttributeMaxDynamicSharedMemorySize, FRONT_SMEM);
    cudaFuncSetAttribute(gemm_tc_kernel<64>,  cudaFuncAttributeMaxDynamicSharedMemorySize, G64_SMEM);
    cudaFuncSetAttribute(gemm_tc_kernel<128>, cudaFuncAttributeMaxDynamicSharedMemorySize, G128_SMEM);

    zero_kernel<<<1, 512>>>();
    front_kernel<<<1552, FTH, FRONT_SMEM>>>(xyz, points, w0, out);
    finalize_kernel<<<1, 128>>>(64, 0, 0, g0, b0);
    gemm_tc_kernel<64><<<MROWS/256, 256, G64_SMEM>>>(w1, w0, xyz, out);
    finalize_kernel<<<1, 128>>>(64, 128, 64, g1, b1);
    gemm_tc_kernel<128><<<MROWS/256, 256, G128_SMEM>>>(w2, nullptr, nullptr, nullptr);
    finalize_kernel<<<1, 128>>>(128, 256, 128, g2, b2);
    output_kernel<<<NB*NS, 128>>>(out);
    (void)in_sizes; (void)n_in; (void)out_size;
}